// round 11
// baseline (speedup 1.0000x reference)
#include <cuda_runtime.h>
#include <cuda_fp16.h>
#include <math.h>
#include <cstdint>

#define Bb 8
#define Mm 128
#define HID 256
#define NROWS_E (Bb*Mm*Mm)   // 131072
#define NROWS_N (Bb*Mm)      // 1024
#define QK_SCALE 0.17677669529663687f  // 1/sqrt(32)

// -------- scratch (device globals) --------
__device__ __align__(16) __half g_k16[(size_t)NROWS_E * HID];  // 67 MB fp16 k
__device__ __align__(16) __half g_a16[(size_t)NROWS_E * HID];  // 67 MB fp16 edge
__device__ float g_q[NROWS_N * HID];
__device__ float g_v[NROWS_N * HID];
__device__ float g_S[64 * 128 * 128];
__device__ float g_St[64 * 128 * 128];        // transposed scores
__device__ float g_msg[64 * 128 * 128];
__device__ float g_nodeh[NROWS_N * HID];
__device__ float g_rmax[64 * 128];
__device__ float g_rsum[64 * 128];            // reciprocal
__device__ float g_cmax[64 * 128];
__device__ float g_csum[64 * 128];            // reciprocal
__device__ __align__(16) __half g_wk16[HID * HID];
__device__ __align__(16) __half g_we16[HID * HID];

__device__ __forceinline__ float mish_f(float x) {
    if (x > 20.f) return x;
    float t = 1.f + __expf(x);
    float t2 = t * t;
    return x * __fdividef(t2 - 1.f, t2 + 1.f);
}

__device__ __forceinline__ uint32_t smem_u32(const void* p) {
    uint32_t a;
    asm("{ .reg .u64 t; cvta.to.shared.u64 t, %1; cvt.u32.u64 %0, t; }" : "=r"(a) : "l"(p));
    return a;
}
__device__ __forceinline__ void ldsm4(uint32_t* r, uint32_t addr) {
    asm volatile("ldmatrix.sync.aligned.m8n8.x4.shared.b16 {%0,%1,%2,%3}, [%4];"
        : "=r"(r[0]), "=r"(r[1]), "=r"(r[2]), "=r"(r[3]) : "r"(addr));
}
__device__ __forceinline__ void mma_f16(float* d, const uint32_t* a, const uint32_t* b) {
    asm volatile("mma.sync.aligned.m16n8k16.row.col.f32.f16.f16.f32 "
        "{%0,%1,%2,%3}, {%4,%5,%6,%7}, {%8,%9}, {%0,%1,%2,%3};"
        : "+f"(d[0]), "+f"(d[1]), "+f"(d[2]), "+f"(d[3])
        : "r"(a[0]), "r"(a[1]), "r"(a[2]), "r"(a[3]), "r"(b[0]), "r"(b[1]));
}
#define CP16(dst, src) asm volatile("cp.async.cg.shared.global [%0], [%1], 16;" :: "r"(dst), "l"(src))
#define CP_COMMIT() asm volatile("cp.async.commit_group;" ::: "memory")
#define CP_WAIT0()  asm volatile("cp.async.wait_group 0;" ::: "memory")
#define CP_WAIT1()  asm volatile("cp.async.wait_group 1;" ::: "memory")

// ============================================================
// prep: edge fp32 -> fp16, plus W conversions in first blocks
// ============================================================
__global__ void __launch_bounds__(256) prep_kernel(const float* __restrict__ E,
                                                   const float* __restrict__ Wk,
                                                   const float* __restrict__ We)
{
    size_t e0 = ((size_t)blockIdx.x * 256 + threadIdx.x) * 8;
    float4 f0 = *(const float4*)(E + e0);
    float4 f1 = *(const float4*)(E + e0 + 4);
    union { __half2 h[4]; uint4 u; } o;
    o.h[0] = __floats2half2_rn(f0.x, f0.y);
    o.h[1] = __floats2half2_rn(f0.z, f0.w);
    o.h[2] = __floats2half2_rn(f1.x, f1.y);
    o.h[3] = __floats2half2_rn(f1.z, f1.w);
    *(uint4*)(g_a16 + e0) = o.u;
    if (blockIdx.x < 256) {
        int t = blockIdx.x * 256 + threadIdx.x;    // 65536 W elements
        g_wk16[t] = __float2half_rn(Wk[t]);
        g_we16[t] = __float2half_rn(We[t]);
    }
}

// ============================================================
// fp16 tensor GEMM: C[131072,256] = act(A' @ W^T + bias)
// A' = A (MSG: scaled per (row, head=chunk) by g_msg, fused).
// SCORES: emit S[b,h,m,n] AND St[b,h,n,m] from the accumulators.
// BM=64 BN=128 BK=32, 8 warps (warp tile 32x32), 3 CTAs/SM.
// ============================================================
#define ST_A    0
#define ST_B    5120
#define ST_MSG  15360
#define ST_SZ   15872
#define TG_SMEM (3 * ST_SZ)

template<bool MSG, bool OUT16, bool ACT, bool SCORES>
__global__ void __launch_bounds__(256, 3) tgemm_kernel(
    const __half* __restrict__ A, const __half* __restrict__ W,
    const float* __restrict__ bias, void* __restrict__ Cv)
{
    extern __shared__ char smem[];
    const uint32_t sb = smem_u32(smem);
    const int tid = threadIdx.x;
    const int wid = tid >> 5, lane = tid & 31;
    const int wm = wid >> 2, wn = wid & 3;      // warp tile rows wm*32, cols wn*32
    const int col0 = blockIdx.x * 128;
    const int r0 = blockIdx.y * 64;

    int mb_base = 0;
    if (MSG) {
        int b = r0 >> 14, m = (r0 >> 7) & 127, n0 = r0 & 127;
        mb_base = b * 131072 + m * 128 + n0;    // + c*16384 per chunk
    }

    float acc[2][4][4];
    #pragma unroll
    for (int i = 0; i < 2; i++)
        #pragma unroll
        for (int j = 0; j < 4; j++)
            #pragma unroll
            for (int q = 0; q < 4; q++) acc[i][j][q] = 0.f;

    const uint32_t aA = sb + ST_A + (wm * 32 + (lane & 15)) * 80 + (lane >> 4) * 16;
    const uint32_t bA = sb + ST_B +
        (wn * 32 + ((lane >> 4) & 1) * 8 + (lane & 7)) * 80 + ((lane >> 3) & 1) * 16;

    const int arow = tid >> 2, aq = tid & 3;    // A: 64 rows x 4 chunks

    auto fill = [&](int c, int stg) {
        uint32_t base = sb + stg * ST_SZ;
        CP16(base + ST_A + (uint32_t)(arow * 80 + aq * 16),
             (const char*)(A + (((size_t)(r0 + arow)) << 8) + c * 32 + aq * 8));
        #pragma unroll
        for (int u = 0; u < 2; u++) {
            int idx = tid + 256 * u;            // B: 128 rows x 4 chunks = 512
            int row = idx >> 2, q = idx & 3;
            CP16(base + ST_B + (uint32_t)(row * 80 + q * 16),
                 (const char*)(W + (((size_t)(col0 + row)) << 8) + c * 32 + q * 8));
        }
        if (MSG && tid < 16)
            CP16(base + ST_MSG + (uint32_t)(tid * 16),
                 (const char*)(g_msg + mb_base + c * 16384 + tid * 4));
        CP_COMMIT();
    };

    fill(0, 0);
    fill(1, 1);
    #pragma unroll 1
    for (int c = 0; c < 8; c++) {
        if (c < 7) CP_WAIT1(); else CP_WAIT0();
        __syncthreads();
        if (c < 6) fill(c + 2, (c + 2) % 3);
        const uint32_t soff = (uint32_t)((c % 3) * ST_SZ);

        // msg scales for this chunk (head == c).
        // mma m16n8k16 A-fragment: regs {a0,a2} hold row g=lane>>2,
        // regs {a1,a3} hold row g+8 (within each 16-row tile).
        __half2 s00, s01, s10, s11;
        if (MSG) {
            const float* sp = (const float*)(smem + (c % 3) * ST_SZ + ST_MSG);
            int g = lane >> 2;
            s00 = __half2half2(__float2half_rn(sp[wm * 32 + g]));
            s01 = __half2half2(__float2half_rn(sp[wm * 32 + g + 8]));
            s10 = __half2half2(__float2half_rn(sp[wm * 32 + 16 + g]));
            s11 = __half2half2(__float2half_rn(sp[wm * 32 + 16 + g + 8]));
        }

        const uint32_t ab = aA + soff;
        const uint32_t bb = bA + soff;
        #pragma unroll
        for (int ks = 0; ks < 2; ks++) {
            const uint32_t koff = ks * 32;
            uint32_t ah[8], bf[8];
            ldsm4(&ah[0], ab + koff);
            ldsm4(&ah[4], ab + 16 * 80 + koff);
            ldsm4(&bf[0], bb + koff);
            ldsm4(&bf[4], bb + 16 * 80 + koff);
            if (MSG) {
                __half2* h = reinterpret_cast<__half2*>(ah);
                h[0] = __hmul2(h[0], s00); h[2] = __hmul2(h[2], s00);
                h[1] = __hmul2(h[1], s01); h[3] = __hmul2(h[3], s01);
                h[4] = __hmul2(h[4], s10); h[6] = __hmul2(h[6], s10);
                h[5] = __hmul2(h[5], s11); h[7] = __hmul2(h[7], s11);
            }
            #pragma unroll
            for (int mt = 0; mt < 2; mt++)
                #pragma unroll
                for (int nt = 0; nt < 4; nt++)
                    mma_f16(acc[mt][nt], &ah[mt * 4], &bf[(nt >> 1) * 4 + (nt & 1) * 2]);
        }
    }

    // q values for fused scores (warp's 32 cols = head bx*4+wn)
    float qv[4][2];
    float dotR[4] = {0.f, 0.f, 0.f, 0.f};
    if (SCORES) {
        int b = r0 >> 14, m = (r0 >> 7) & 127;
        const float* qrow = g_q + (size_t)(b * 128 + m) * 256 + col0 + wn * 32 + (lane & 3) * 2;
        #pragma unroll
        for (int nt = 0; nt < 4; nt++) { qv[nt][0] = qrow[nt * 8]; qv[nt][1] = qrow[nt * 8 + 1]; }
    }

    // epilogue
    #pragma unroll
    for (int nt = 0; nt < 4; nt++) {
        const int col = col0 + wn * 32 + nt * 8 + (lane & 3) * 2;
        const float b0 = bias[col], b1 = bias[col + 1];
        #pragma unroll
        for (int mt = 0; mt < 2; mt++) {
            int row = r0 + wm * 32 + mt * 16 + (lane >> 2);
            float v0 = acc[mt][nt][0] + b0, v1 = acc[mt][nt][1] + b1;
            float v2 = acc[mt][nt][2] + b0, v3 = acc[mt][nt][3] + b1;
            if (SCORES) {
                dotR[2 * mt]     += v0 * qv[nt][0] + v1 * qv[nt][1];
                dotR[2 * mt + 1] += v2 * qv[nt][0] + v3 * qv[nt][1];
            }
            if (ACT) { v0 = mish_f(v0); v1 = mish_f(v1); v2 = mish_f(v2); v3 = mish_f(v3); }
            if (OUT16) {
                __half* C = (__half*)Cv;
                *(__half2*)(C + (size_t)row * 256 + col) = __floats2half2_rn(v0, v1);
                *(__half2*)(C + (size_t)(row + 8) * 256 + col) = __floats2half2_rn(v2, v3);
            } else {
                float* C = (float*)Cv;
                float2 p0; p0.x = v0; p0.y = v1;
                float2 p1; p1.x = v2; p1.y = v3;
                *(float2*)(C + (size_t)row * 256 + col) = p0;
                *(float2*)(C + (size_t)(row + 8) * 256 + col) = p1;
            }
        }
    }

    if (SCORES) {
        #pragma unroll
        for (int i = 0; i < 4; i++) {
            dotR[i] += __shfl_xor_sync(0xffffffffu, dotR[i], 1);
            dotR[i] += __shfl_xor_sync(0xffffffffu, dotR[i], 2);
        }
        if ((lane & 3) == 0) {
            int b = r0 >> 14, m = (r0 >> 7) & 127, n0 = r0 & 127;
            int h = blockIdx.x * 4 + wn;
            int g = lane >> 2;
            float s0 = dotR[0] * QK_SCALE, s1 = dotR[1] * QK_SCALE;
            float s2 = dotR[2] * QK_SCALE, s3 = dotR[3] * QK_SCALE;
            float* Sp = g_S + (((size_t)(b * 8 + h) * 128) + m) * 128 + n0 + wm * 32;
            Sp[g] = s0; Sp[g + 8] = s1; Sp[g + 16] = s2; Sp[g + 24] = s3;
            float* Stp = g_St + (((size_t)(b * 8 + h) * 128) + n0 + wm * 32) * 128 + m;
            Stp[(size_t)g * 128] = s0;
            Stp[(size_t)(g + 8) * 128] = s1;
            Stp[(size_t)(g + 16) * 128] = s2;
            Stp[(size_t)(g + 24) * 128] = s3;
        }
    }
}

// ============================================================
// fp32 SGEMM core for the small (1024-row) projections
// ============================================================
template<bool ACT>
__device__ __forceinline__ void gemm_core(
    const float* __restrict__ A, const float* __restrict__ W,
    const float* __restrict__ bias, float* __restrict__ C,
    int row0, int col0)
{
    __shared__ __align__(16) float As[16][132];
    __shared__ __align__(16) float Bs[16][68];

    const int t  = threadIdx.x;
    const int tx = t & 15;
    const int ty = t >> 4;
    const int lr = t >> 2;
    const int lc = (t & 3) << 2;
    const int gr1 = row0 + lr;
    const int gr2 = gr1 + 64;

    float acc[8][4];
    #pragma unroll
    for (int i = 0; i < 8; i++)
        #pragma unroll
        for (int j = 0; j < 4; j++) acc[i][j] = 0.f;

    for (int k0 = 0; k0 < HID; k0 += 16) {
        float4 a1 = *(const float4*)(A + (size_t)gr1 * HID + k0 + lc);
        float4 a2 = *(const float4*)(A + (size_t)gr2 * HID + k0 + lc);
        As[lc + 0][lr] = a1.x; As[lc + 1][lr] = a1.y;
        As[lc + 2][lr] = a1.z; As[lc + 3][lr] = a1.w;
        As[lc + 0][lr + 64] = a2.x; As[lc + 1][lr + 64] = a2.y;
        As[lc + 2][lr + 64] = a2.z; As[lc + 3][lr + 64] = a2.w;
        float4 b4 = *(const float4*)(W + (size_t)(col0 + lr) * HID + k0 + lc);
        Bs[lc + 0][lr] = b4.x; Bs[lc + 1][lr] = b4.y;
        Bs[lc + 2][lr] = b4.z; Bs[lc + 3][lr] = b4.w;
        __syncthreads();
        #pragma unroll
        for (int kk = 0; kk < 16; kk++) {
            float4 alo = *(const float4*)&As[kk][ty * 8];
            float4 ahi = *(const float4*)&As[kk][ty * 8 + 4];
            float4 bv  = *(const float4*)&Bs[kk][tx * 4];
            float avv[8] = {alo.x, alo.y, alo.z, alo.w, ahi.x, ahi.y, ahi.z, ahi.w};
            float bw[4] = {bv.x, bv.y, bv.z, bv.w};
            #pragma unroll
            for (int i = 0; i < 8; i++)
                #pragma unroll
                for (int j = 0; j < 4; j++)
                    acc[i][j] = fmaf(avv[i], bw[j], acc[i][j]);
        }
        __syncthreads();
    }

    float4 bb = *(const float4*)(bias + col0 + tx * 4);
    float bias4[4] = {bb.x, bb.y, bb.z, bb.w};
    #pragma unroll
    for (int i = 0; i < 8; i++) {
        float v0 = acc[i][0] + bias4[0];
        float v1 = acc[i][1] + bias4[1];
        float v2 = acc[i][2] + bias4[2];
        float v3 = acc[i][3] + bias4[3];
        if (ACT) { v0 = mish_f(v0); v1 = mish_f(v1); v2 = mish_f(v2); v3 = mish_f(v3); }
        float4 o; o.x = v0; o.y = v1; o.z = v2; o.w = v3;
        *(float4*)(C + (size_t)(row0 + ty * 8 + i) * HID + col0 + tx * 4) = o;
    }
}

__global__ void __launch_bounds__(256)
gemm_qv_kernel(const float* __restrict__ node,
               const float* __restrict__ Wq, const float* __restrict__ bq,
               const float* __restrict__ Wv, const float* __restrict__ bv,
               float* __restrict__ Cq, float* __restrict__ Cv)
{
    int by = blockIdx.y;
    if (by < 4) gemm_core<false>(node, Wq, bq, Cq, blockIdx.x * 128, by * 64);
    else        gemm_core<false>(node, Wv, bv, Cv, blockIdx.x * 128, (by - 4) * 64);
}

__global__ void __launch_bounds__(256)
gemm_node_kernel(const float* __restrict__ A, const float* __restrict__ W,
                 const float* __restrict__ bias, float* __restrict__ C)
{
    gemm_core<true>(A, W, bias, C, blockIdx.x * 128, blockIdx.y * 64);
}

// ============================================================
// stats: one warp per (kind, bh, i).
// kind 0: row stats over S[bh,i,:]; kind 1: col stats over St[bh,i,:].
// ============================================================
__global__ void __launch_bounds__(256) stats_kernel(const float* __restrict__ mask)
{
    const int id = blockIdx.x * 8 + (threadIdx.x >> 5);   // 0..16383
    const int lane = threadIdx.x & 31;
    const int kind = id >> 13;
    const int rem = id & 8191;
    const int bh = rem >> 7, i = rem & 127, b = bh >> 3;

    const float* src = (kind ? g_St : g_S) + (size_t)bh * 16384 + i * 128 + lane * 4;
    float4 v = *(const float4*)src;
    float4 mk = *(const float4*)(mask + b * 128 + lane * 4);

    float x0 = (mk.x != 0.f) ? v.x : -1e30f;
    float x1 = (mk.y != 0.f) ? v.y : -1e30f;
    float x2 = (mk.z != 0.f) ? v.z : -1e30f;
    float x3 = (mk.w != 0.f) ? v.w : -1e30f;
    float mx = fmaxf(fmaxf(x0, x1), fmaxf(x2, x3));
    #pragma unroll
    for (int s = 16; s > 0; s >>= 1) mx = fmaxf(mx, __shfl_xor_sync(0xffffffffu, mx, s));

    float sm = ((mk.x != 0.f) ? __expf(x0 - mx) : 0.f)
             + ((mk.y != 0.f) ? __expf(x1 - mx) : 0.f)
             + ((mk.z != 0.f) ? __expf(x2 - mx) : 0.f)
             + ((mk.w != 0.f) ? __expf(x3 - mx) : 0.f);
    #pragma unroll
    for (int s = 16; s > 0; s >>= 1) sm += __shfl_xor_sync(0xffffffffu, sm, s);

    if (lane == 0) {
        if (kind) { g_cmax[bh * 128 + i] = mx; g_csum[bh * 128 + i] = 1.f / sm; }
        else      { g_rmax[bh * 128 + i] = mx; g_rsum[bh * 128 + i] = 1.f / sm; }
    }
}

// ============================================================
// message: elementwise, fully coalesced via S and St.
// ============================================================
__global__ void __launch_bounds__(256) message_kernel(
    const float* __restrict__ dist, const float* __restrict__ mask,
    const float* __restrict__ lamp)
{
    const int bh = blockIdx.x, b = bh >> 3, t = threadIdx.x;
    const int base = blockIdx.y * 2048;
    const float lam = lamp[0];
    __shared__ float mks[128];
    if (t < 128) mks[t] = mask[b * 128 + t];
    __syncthreads();

    const float* Sp  = g_S  + (size_t)bh * 16384;
    const float* Stp = g_St + (size_t)bh * 16384;
    const float* db  = dist + (size_t)b * 16384;
    float* mb = g_msg + (size_t)bh * 16384;

    #pragma unroll
    for (int r = 0; r < 8; r++) {
        int idx = base + t + 256 * r;
        int i = idx >> 7, j = idx & 127;
        float outv = 0.f;
        if (mks[j] != 0.f) {
            float o  = __expf(Sp[idx]  - g_rmax[bh * 128 + i]) * g_rsum[bh * 128 + i];
            float in = __expf(Stp[idx] - g_cmax[bh * 128 + i]) * g_csum[bh * 128 + i];
            float val = (i == j) ? in : (o + in);
            outv = val * __expf(-lam * db[idx]);
        }
        mb[idx] = outv;
    }
}

// ============================================================
// node_hidden: msg tile staged in padded smem (conflict-free)
// ============================================================
#define NODEH_SMEM ((128 * 32 + 128 * 129) * 4)
__global__ void __launch_bounds__(256) nodeh_kernel()
{
    extern __shared__ float sm_[];
    float* vs = sm_;              // 128 x 32
    float* ms = sm_ + 128 * 32;   // 128 x 129 (padded)
    const int bh = blockIdx.x;
    const int b = bh >> 3, h = bh & 7;
    const int t = threadIdx.x;
    #pragma unroll
    for (int r = 0; r < 4; r++) {
        int idx4 = t + 256 * r;
        int n = idx4 >> 3;
        int c = (idx4 & 7) * 4;
        *(float4*)&vs[n * 32 + c] =
            *(const float4*)(g_v + (size_t)(b * 128 + n) * 256 + h * 32 + c);
    }
    #pragma unroll
    for (int r = 0; r < 16; r++) {
        int idx4 = t + 256 * r;                 // 4096 float4s
        int i = idx4 >> 5, j = (idx4 & 31) * 4;
        float4 v = *(const float4*)(g_msg + (size_t)bh * 16384 + i * 128 + j);
        float* d = ms + i * 129 + j;
        d[0] = v.x; d[1] = v.y; d[2] = v.z; d[3] = v.w;
    }
    __syncthreads();
    const int m = t & 127;
    const int dbase = (t >> 7) * 16;
    const float* mrow = ms + m * 129;
    float acc[16];
    #pragma unroll
    for (int d = 0; d < 16; d++) acc[d] = 0.f;
    for (int n = 0; n < 128; n++) {
        float w = mrow[n];
        const float* vr = &vs[n * 32 + dbase];
        #pragma unroll
        for (int d = 0; d < 16; d++) acc[d] = fmaf(w, vr[d], acc[d]);
    }
    float* outp = g_nodeh + (size_t)(b * 128 + m) * 256 + h * 32 + dbase;
    #pragma unroll
    for (int d = 0; d < 16; d++) outp[d] = acc[d];
}

// ============================================================
extern "C" void kernel_launch(void* const* d_in, const int* in_sizes, int n_in,
                              void* d_out, int out_size)
{
    const float* node = (const float*)d_in[0];
    const float* edge = (const float*)d_in[1];
    const float* dist = (const float*)d_in[2];
    const float* mask = (const float*)d_in[3];
    const float* lam  = (const float*)d_in[4];
    const float* Wq = (const float*)d_in[5];  const float* bq = (const float*)d_in[6];
    const float* Wk = (const float*)d_in[7];  const float* bk = (const float*)d_in[8];
    const float* Wv = (const float*)d_in[9];  const float* bv = (const float*)d_in[10];
    const float* Wn = (const float*)d_in[11]; const float* bn = (const float*)d_in[12];
    const float* We = (const float*)d_in[13]; const float* be = (const float*)d_in[14];

    float* out = (float*)d_out;
    float* node_out = out;
    float* edge_out = out + (size_t)NROWS_N * HID;

    float *pq, *pv, *pnh;
    __half *pa16, *pk16, *pwk16, *pwe16;
    cudaGetSymbolAddress((void**)&pq, g_q);
    cudaGetSymbolAddress((void**)&pv, g_v);
    cudaGetSymbolAddress((void**)&pnh, g_nodeh);
    cudaGetSymbolAddress((void**)&pa16, g_a16);
    cudaGetSymbolAddress((void**)&pk16, g_k16);
    cudaGetSymbolAddress((void**)&pwk16, g_wk16);
    cudaGetSymbolAddress((void**)&pwe16, g_we16);

    cudaFuncSetAttribute((const void*)tgemm_kernel<false, true, false, true>,
                         cudaFuncAttributeMaxDynamicSharedMemorySize, TG_SMEM);
    cudaFuncSetAttribute((const void*)tgemm_kernel<true, false, true, false>,
                         cudaFuncAttributeMaxDynamicSharedMemorySize, TG_SMEM);
    cudaFuncSetAttribute((const void*)nodeh_kernel,
                         cudaFuncAttributeMaxDynamicSharedMemorySize, NODEH_SMEM);

    // persistent side stream + events (host-side infra; created once,
    // identical captured work every call)
    static cudaStream_t s1 = nullptr;
    static cudaEvent_t evA = nullptr, evB = nullptr, evC = nullptr, evD = nullptr;
    if (!s1) {
        cudaStreamCreateWithFlags(&s1, cudaStreamNonBlocking);
        cudaEventCreateWithFlags(&evA, cudaEventDisableTiming);
        cudaEventCreateWithFlags(&evB, cudaEventDisableTiming);
        cudaEventCreateWithFlags(&evC, cudaEventDisableTiming);
        cudaEventCreateWithFlags(&evD, cudaEventDisableTiming);
    }

    dim3 gT(2, NROWS_E / 64);           // (2 col blocks, 2048 row blocks)

    // fork: side stream runs gemm_qv while main stream runs prep
    cudaEventRecord(evA, 0);
    cudaStreamWaitEvent(s1, evA, 0);

    prep_kernel<<<16384, 256>>>(edge, Wk, We);                       // s0
    gemm_qv_kernel<<<dim3(8, 8), 256, 0, s1>>>(node, Wq, bq, Wv, bv, pq, pv);  // s1
    cudaEventRecord(evB, s1);
    cudaStreamWaitEvent(0, evB, 0);     // tgemm1 needs q (SCORES epilogue)

    tgemm_kernel<false, true, false, true><<<gT, 256, TG_SMEM>>>(pa16, pwk16, bk, (void*)pk16);
    stats_kernel<<<2048, 256>>>(mask);
    message_kernel<<<dim3(64, 8), 256>>>(dist, mask, lam);

    // fork: nodeh + node GEMM run on s1 concurrently with tgemm2
    cudaEventRecord(evC, 0);
    cudaStreamWaitEvent(s1, evC, 0);

    tgemm_kernel<true, false, true, false><<<gT, 256, TG_SMEM>>>(pk16, pwe16, be, edge_out);   // s0
    nodeh_kernel<<<64, 256, NODEH_SMEM, s1>>>();                                               // s1
    gemm_node_kernel<<<dim3(8, 4), 256, 0, s1>>>(pnh, Wn, bn, node_out);                       // s1

    // join
    cudaEventRecord(evD, s1);
    cudaStreamWaitEvent(0, evD, 0);
}

// round 12
// speedup vs baseline: 1.1430x; 1.1430x over previous
#include <cuda_runtime.h>
#include <cuda_fp16.h>
#include <math.h>
#include <cstdint>

#define Bb 8
#define Mm 128
#define HID 256
#define NROWS_E (Bb*Mm*Mm)   // 131072
#define NROWS_N (Bb*Mm)      // 1024
#define QK_SCALE 0.17677669529663687f  // 1/sqrt(32)

// -------- scratch (device globals) --------
__device__ __align__(16) __half g_k16[(size_t)NROWS_E * HID];  // 67 MB fp16 k
__device__ float g_q[NROWS_N * HID];
__device__ float g_v[NROWS_N * HID];
__device__ float g_S[64 * 128 * 128];
__device__ float g_St[64 * 128 * 128];        // transposed scores
__device__ float g_msg[64 * 128 * 128];
__device__ float g_nodeh[NROWS_N * HID];
__device__ float g_rmax[64 * 128];
__device__ float g_rsum[64 * 128];            // reciprocal
__device__ float g_cmax[64 * 128];
__device__ float g_csum[64 * 128];            // reciprocal
__device__ __align__(16) __half g_wk16[HID * HID];
__device__ __align__(16) __half g_we16[HID * HID];

__device__ __forceinline__ float mish_f(float x) {
    if (x > 20.f) return x;
    float t = 1.f + __expf(x);
    float t2 = t * t;
    return x * __fdividef(t2 - 1.f, t2 + 1.f);
}

__device__ __forceinline__ uint32_t smem_u32(const void* p) {
    uint32_t a;
    asm("{ .reg .u64 t; cvta.to.shared.u64 t, %1; cvt.u32.u64 %0, t; }" : "=r"(a) : "l"(p));
    return a;
}
__device__ __forceinline__ void ldsm4(uint32_t* r, uint32_t addr) {
    asm volatile("ldmatrix.sync.aligned.m8n8.x4.shared.b16 {%0,%1,%2,%3}, [%4];"
        : "=r"(r[0]), "=r"(r[1]), "=r"(r[2]), "=r"(r[3]) : "r"(addr));
}
__device__ __forceinline__ void mma_f16(float* d, const uint32_t* a, const uint32_t* b) {
    asm volatile("mma.sync.aligned.m16n8k16.row.col.f32.f16.f16.f32 "
        "{%0,%1,%2,%3}, {%4,%5,%6,%7}, {%8,%9}, {%0,%1,%2,%3};"
        : "+f"(d[0]), "+f"(d[1]), "+f"(d[2]), "+f"(d[3])
        : "r"(a[0]), "r"(a[1]), "r"(a[2]), "r"(a[3]), "r"(b[0]), "r"(b[1]));
}
#define CP16(dst, src) asm volatile("cp.async.cg.shared.global [%0], [%1], 16;" :: "r"(dst), "l"(src))
#define CP_COMMIT() asm volatile("cp.async.commit_group;" ::: "memory")
#define CP_WAIT0()  asm volatile("cp.async.wait_group 0;" ::: "memory")
#define CP_WAIT1()  asm volatile("cp.async.wait_group 1;" ::: "memory")

// ============================================================
// prep: W fp32 -> fp16 (tiny)
// ============================================================
__global__ void __launch_bounds__(256) prep_w_kernel(const float* __restrict__ Wk,
                                                     const float* __restrict__ We)
{
    int t = blockIdx.x * 256 + threadIdx.x;    // 65536 W elements
    g_wk16[t] = __float2half_rn(Wk[t]);
    g_we16[t] = __float2half_rn(We[t]);
}

// ============================================================
// fp16 tensor GEMM: C[131072,256] = act(A' @ W^T + bias)
// AF32: A is fp32 in gmem; converted to fp16 on the fly
//       (register-prefetch one chunk ahead, cvt+STS at stage fill).
// MSG:  A scaled per (row, head=chunk) by g_msg, fused.
// SCORES: emit S[b,h,m,n] AND St[b,h,n,m] from the accumulators.
// BM=64 BN=128 BK=32, 8 warps (warp tile 32x32), 3 CTAs/SM.
// ============================================================
#define ST_A    0
#define ST_B    5120
#define ST_MSG  15360
#define ST_SZ   15872
#define TG_SMEM (3 * ST_SZ)

template<bool AF32, bool MSG, bool OUT16, bool ACT, bool SCORES>
__global__ void __launch_bounds__(256, 3) tgemm_kernel(
    const void* __restrict__ Av, const __half* __restrict__ W,
    const float* __restrict__ bias, void* __restrict__ Cv)
{
    extern __shared__ char smem[];
    const uint32_t sb = smem_u32(smem);
    const int tid = threadIdx.x;
    const int wid = tid >> 5, lane = tid & 31;
    const int wm = wid >> 2, wn = wid & 3;      // warp tile rows wm*32, cols wn*32
    const int col0 = blockIdx.x * 128;
    const int r0 = blockIdx.y * 64;

    const __half* A16 = (const __half*)Av;
    const float*  A32 = (const float*)Av;

    int mb_base = 0;
    if (MSG) {
        int b = r0 >> 14, m = (r0 >> 7) & 127, n0 = r0 & 127;
        mb_base = b * 131072 + m * 128 + n0;    // + c*16384 per chunk
    }

    float acc[2][4][4];
    #pragma unroll
    for (int i = 0; i < 2; i++)
        #pragma unroll
        for (int j = 0; j < 4; j++)
            #pragma unroll
            for (int q = 0; q < 4; q++) acc[i][j][q] = 0.f;

    const uint32_t aA = sb + ST_A + (wm * 32 + (lane & 15)) * 80 + (lane >> 4) * 16;
    const uint32_t bA = sb + ST_B +
        (wn * 32 + ((lane >> 4) & 1) * 8 + (lane & 7)) * 80 + ((lane >> 3) & 1) * 16;

    const int arow = tid >> 2, aq = tid & 3;    // A: 64 rows x 4 chunks

    auto fill = [&](int c, int stg) {
        uint32_t base = sb + stg * ST_SZ;
        if (!AF32)
            CP16(base + ST_A + (uint32_t)(arow * 80 + aq * 16),
                 (const char*)(A16 + (((size_t)(r0 + arow)) << 8) + c * 32 + aq * 8));
        #pragma unroll
        for (int u = 0; u < 2; u++) {
            int idx = tid + 256 * u;            // B: 128 rows x 4 chunks = 512
            int row = idx >> 2, q = idx & 3;
            CP16(base + ST_B + (uint32_t)(row * 80 + q * 16),
                 (const char*)(W + (((size_t)(col0 + row)) << 8) + c * 32 + q * 8));
        }
        if (MSG && tid < 16)
            CP16(base + ST_MSG + (uint32_t)(tid * 16),
                 (const char*)(g_msg + mb_base + c * 16384 + tid * 4));
        CP_COMMIT();
    };
    auto ldA = [&](int c, float4& f0, float4& f1) {
        const float* p = A32 + (((size_t)(r0 + arow)) << 8) + c * 32 + aq * 8;
        f0 = *(const float4*)p;
        f1 = *(const float4*)(p + 4);
    };
    auto cvtstA = [&](int stg, const float4& f0, const float4& f1) {
        union { __half2 h[4]; uint4 u; } o;
        o.h[0] = __floats2half2_rn(f0.x, f0.y);
        o.h[1] = __floats2half2_rn(f0.z, f0.w);
        o.h[2] = __floats2half2_rn(f1.x, f1.y);
        o.h[3] = __floats2half2_rn(f1.z, f1.w);
        *(uint4*)(smem + stg * ST_SZ + ST_A + arow * 80 + aq * 16) = o.u;
    };

    float4 pa0, pa1;
    if (AF32) {
        ldA(0, pa0, pa1); cvtstA(0, pa0, pa1);
        ldA(1, pa0, pa1); cvtstA(1, pa0, pa1);
        ldA(2, pa0, pa1);                 // prefetch chunk 2
    }
    fill(0, 0);
    fill(1, 1);
    #pragma unroll 1
    for (int c = 0; c < 8; c++) {
        if (c < 7) CP_WAIT1(); else CP_WAIT0();
        __syncthreads();
        if (c < 6) {
            fill(c + 2, (c + 2) % 3);
            if (AF32) {
                cvtstA((c + 2) % 3, pa0, pa1);     // store chunk c+2
                if (c < 5) ldA(c + 3, pa0, pa1);   // prefetch chunk c+3
            }
        }
        const uint32_t soff = (uint32_t)((c % 3) * ST_SZ);

        // msg scales for this chunk (head == c).
        // mma m16n8k16 A-fragment: regs {a0,a2} hold row g=lane>>2,
        // regs {a1,a3} hold row g+8 (within each 16-row tile).
        __half2 s00, s01, s10, s11;
        if (MSG) {
            const float* sp = (const float*)(smem + (c % 3) * ST_SZ + ST_MSG);
            int g = lane >> 2;
            s00 = __half2half2(__float2half_rn(sp[wm * 32 + g]));
            s01 = __half2half2(__float2half_rn(sp[wm * 32 + g + 8]));
            s10 = __half2half2(__float2half_rn(sp[wm * 32 + 16 + g]));
            s11 = __half2half2(__float2half_rn(sp[wm * 32 + 16 + g + 8]));
        }

        const uint32_t ab = aA + soff;
        const uint32_t bb = bA + soff;
        #pragma unroll
        for (int ks = 0; ks < 2; ks++) {
            const uint32_t koff = ks * 32;
            uint32_t ah[8], bf[8];
            ldsm4(&ah[0], ab + koff);
            ldsm4(&ah[4], ab + 16 * 80 + koff);
            ldsm4(&bf[0], bb + koff);
            ldsm4(&bf[4], bb + 16 * 80 + koff);
            if (MSG) {
                __half2* h = reinterpret_cast<__half2*>(ah);
                h[0] = __hmul2(h[0], s00); h[2] = __hmul2(h[2], s00);
                h[1] = __hmul2(h[1], s01); h[3] = __hmul2(h[3], s01);
                h[4] = __hmul2(h[4], s10); h[6] = __hmul2(h[6], s10);
                h[5] = __hmul2(h[5], s11); h[7] = __hmul2(h[7], s11);
            }
            #pragma unroll
            for (int mt = 0; mt < 2; mt++)
                #pragma unroll
                for (int nt = 0; nt < 4; nt++)
                    mma_f16(acc[mt][nt], &ah[mt * 4], &bf[(nt >> 1) * 4 + (nt & 1) * 2]);
        }
    }

    // q values for fused scores (warp's 32 cols = head bx*4+wn)
    float qv[4][2];
    float dotR[4] = {0.f, 0.f, 0.f, 0.f};
    if (SCORES) {
        int b = r0 >> 14, m = (r0 >> 7) & 127;
        const float* qrow = g_q + (size_t)(b * 128 + m) * 256 + col0 + wn * 32 + (lane & 3) * 2;
        #pragma unroll
        for (int nt = 0; nt < 4; nt++) { qv[nt][0] = qrow[nt * 8]; qv[nt][1] = qrow[nt * 8 + 1]; }
    }

    // epilogue
    #pragma unroll
    for (int nt = 0; nt < 4; nt++) {
        const int col = col0 + wn * 32 + nt * 8 + (lane & 3) * 2;
        const float b0 = bias[col], b1 = bias[col + 1];
        #pragma unroll
        for (int mt = 0; mt < 2; mt++) {
            int row = r0 + wm * 32 + mt * 16 + (lane >> 2);
            float v0 = acc[mt][nt][0] + b0, v1 = acc[mt][nt][1] + b1;
            float v2 = acc[mt][nt][2] + b0, v3 = acc[mt][nt][3] + b1;
            if (SCORES) {
                dotR[2 * mt]     += v0 * qv[nt][0] + v1 * qv[nt][1];
                dotR[2 * mt + 1] += v2 * qv[nt][0] + v3 * qv[nt][1];
            }
            if (ACT) { v0 = mish_f(v0); v1 = mish_f(v1); v2 = mish_f(v2); v3 = mish_f(v3); }
            if (OUT16) {
                __half* C = (__half*)Cv;
                *(__half2*)(C + (size_t)row * 256 + col) = __floats2half2_rn(v0, v1);
                *(__half2*)(C + (size_t)(row + 8) * 256 + col) = __floats2half2_rn(v2, v3);
            } else {
                float* C = (float*)Cv;
                float2 p0; p0.x = v0; p0.y = v1;
                float2 p1; p1.x = v2; p1.y = v3;
                *(float2*)(C + (size_t)row * 256 + col) = p0;
                *(float2*)(C + (size_t)(row + 8) * 256 + col) = p1;
            }
        }
    }

    if (SCORES) {
        #pragma unroll
        for (int i = 0; i < 4; i++) {
            dotR[i] += __shfl_xor_sync(0xffffffffu, dotR[i], 1);
            dotR[i] += __shfl_xor_sync(0xffffffffu, dotR[i], 2);
        }
        if ((lane & 3) == 0) {
            int b = r0 >> 14, m = (r0 >> 7) & 127, n0 = r0 & 127;
            int h = blockIdx.x * 4 + wn;
            int g = lane >> 2;
            float s0 = dotR[0] * QK_SCALE, s1 = dotR[1] * QK_SCALE;
            float s2 = dotR[2] * QK_SCALE, s3 = dotR[3] * QK_SCALE;
            float* Sp = g_S + (((size_t)(b * 8 + h) * 128) + m) * 128 + n0 + wm * 32;
            Sp[g] = s0; Sp[g + 8] = s1; Sp[g + 16] = s2; Sp[g + 24] = s3;
            float* Stp = g_St + (((size_t)(b * 8 + h) * 128) + n0 + wm * 32) * 128 + m;
            Stp[(size_t)g * 128] = s0;
            Stp[(size_t)(g + 8) * 128] = s1;
            Stp[(size_t)(g + 16) * 128] = s2;
            Stp[(size_t)(g + 24) * 128] = s3;
        }
    }
}

// ============================================================
// fp32 SGEMM core for the small (1024-row) projections
// ============================================================
template<bool ACT>
__device__ __forceinline__ void gemm_core(
    const float* __restrict__ A, const float* __restrict__ W,
    const float* __restrict__ bias, float* __restrict__ C,
    int row0, int col0)
{
    __shared__ __align__(16) float As[16][132];
    __shared__ __align__(16) float Bs[16][68];

    const int t  = threadIdx.x;
    const int tx = t & 15;
    const int ty = t >> 4;
    const int lr = t >> 2;
    const int lc = (t & 3) << 2;
    const int gr1 = row0 + lr;
    const int gr2 = gr1 + 64;

    float acc[8][4];
    #pragma unroll
    for (int i = 0; i < 8; i++)
        #pragma unroll
        for (int j = 0; j < 4; j++) acc[i][j] = 0.f;

    for (int k0 = 0; k0 < HID; k0 += 16) {
        float4 a1 = *(const float4*)(A + (size_t)gr1 * HID + k0 + lc);
        float4 a2 = *(const float4*)(A + (size_t)gr2 * HID + k0 + lc);
        As[lc + 0][lr] = a1.x; As[lc + 1][lr] = a1.y;
        As[lc + 2][lr] = a1.z; As[lc + 3][lr] = a1.w;
        As[lc + 0][lr + 64] = a2.x; As[lc + 1][lr + 64] = a2.y;
        As[lc + 2][lr + 64] = a2.z; As[lc + 3][lr + 64] = a2.w;
        float4 b4 = *(const float4*)(W + (size_t)(col0 + lr) * HID + k0 + lc);
        Bs[lc + 0][lr] = b4.x; Bs[lc + 1][lr] = b4.y;
        Bs[lc + 2][lr] = b4.z; Bs[lc + 3][lr] = b4.w;
        __syncthreads();
        #pragma unroll
        for (int kk = 0; kk < 16; kk++) {
            float4 alo = *(const float4*)&As[kk][ty * 8];
            float4 ahi = *(const float4*)&As[kk][ty * 8 + 4];
            float4 bv  = *(const float4*)&Bs[kk][tx * 4];
            float avv[8] = {alo.x, alo.y, alo.z, alo.w, ahi.x, ahi.y, ahi.z, ahi.w};
            float bw[4] = {bv.x, bv.y, bv.z, bv.w};
            #pragma unroll
            for (int i = 0; i < 8; i++)
                #pragma unroll
                for (int j = 0; j < 4; j++)
                    acc[i][j] = fmaf(avv[i], bw[j], acc[i][j]);
        }
        __syncthreads();
    }

    float4 bb = *(const float4*)(bias + col0 + tx * 4);
    float bias4[4] = {bb.x, bb.y, bb.z, bb.w};
    #pragma unroll
    for (int i = 0; i < 8; i++) {
        float v0 = acc[i][0] + bias4[0];
        float v1 = acc[i][1] + bias4[1];
        float v2 = acc[i][2] + bias4[2];
        float v3 = acc[i][3] + bias4[3];
        if (ACT) { v0 = mish_f(v0); v1 = mish_f(v1); v2 = mish_f(v2); v3 = mish_f(v3); }
        float4 o; o.x = v0; o.y = v1; o.z = v2; o.w = v3;
        *(float4*)(C + (size_t)(row0 + ty * 8 + i) * HID + col0 + tx * 4) = o;
    }
}

__global__ void __launch_bounds__(256)
gemm_qv_kernel(const float* __restrict__ node,
               const float* __restrict__ Wq, const float* __restrict__ bq,
               const float* __restrict__ Wv, const float* __restrict__ bv,
               float* __restrict__ Cq, float* __restrict__ Cv)
{
    int by = blockIdx.y;
    if (by < 4) gemm_core<false>(node, Wq, bq, Cq, blockIdx.x * 128, by * 64);
    else        gemm_core<false>(node, Wv, bv, Cv, blockIdx.x * 128, (by - 4) * 64);
}

__global__ void __launch_bounds__(256)
gemm_node_kernel(const float* __restrict__ A, const float* __restrict__ W,
                 const float* __restrict__ bias, float* __restrict__ C)
{
    gemm_core<true>(A, W, bias, C, blockIdx.x * 128, blockIdx.y * 64);
}

// ============================================================
// stats: one warp per (kind, bh, i).
// kind 0: row stats over S[bh,i,:]; kind 1: col stats over St[bh,i,:].
// ============================================================
__global__ void __launch_bounds__(256) stats_kernel(const float* __restrict__ mask)
{
    const int id = blockIdx.x * 8 + (threadIdx.x >> 5);   // 0..16383
    const int lane = threadIdx.x & 31;
    const int kind = id >> 13;
    const int rem = id & 8191;
    const int bh = rem >> 7, i = rem & 127, b = bh >> 3;

    const float* src = (kind ? g_St : g_S) + (size_t)bh * 16384 + i * 128 + lane * 4;
    float4 v = *(const float4*)src;
    float4 mk = *(const float4*)(mask + b * 128 + lane * 4);

    float x0 = (mk.x != 0.f) ? v.x : -1e30f;
    float x1 = (mk.y != 0.f) ? v.y : -1e30f;
    float x2 = (mk.z != 0.f) ? v.z : -1e30f;
    float x3 = (mk.w != 0.f) ? v.w : -1e30f;
    float mx = fmaxf(fmaxf(x0, x1), fmaxf(x2, x3));
    #pragma unroll
    for (int s = 16; s > 0; s >>= 1) mx = fmaxf(mx, __shfl_xor_sync(0xffffffffu, mx, s));

    float sm = ((mk.x != 0.f) ? __expf(x0 - mx) : 0.f)
             + ((mk.y != 0.f) ? __expf(x1 - mx) : 0.f)
             + ((mk.z != 0.f) ? __expf(x2 - mx) : 0.f)
             + ((mk.w != 0.f) ? __expf(x3 - mx) : 0.f);
    #pragma unroll
    for (int s = 16; s > 0; s >>= 1) sm += __shfl_xor_sync(0xffffffffu, sm, s);

    if (lane == 0) {
        if (kind) { g_cmax[bh * 128 + i] = mx; g_csum[bh * 128 + i] = 1.f / sm; }
        else      { g_rmax[bh * 128 + i] = mx; g_rsum[bh * 128 + i] = 1.f / sm; }
    }
}

// ============================================================
// message: elementwise, fully coalesced via S and St.
// ============================================================
__global__ void __launch_bounds__(256) message_kernel(
    const float* __restrict__ dist, const float* __restrict__ mask,
    const float* __restrict__ lamp)
{
    const int bh = blockIdx.x, b = bh >> 3, t = threadIdx.x;
    const int base = blockIdx.y * 2048;
    const float lam = lamp[0];
    __shared__ float mks[128];
    if (t < 128) mks[t] = mask[b * 128 + t];
    __syncthreads();

    const float* Sp  = g_S  + (size_t)bh * 16384;
    const float* Stp = g_St + (size_t)bh * 16384;
    const float* db  = dist + (size_t)b * 16384;
    float* mb = g_msg + (size_t)bh * 16384;

    #pragma unroll
    for (int r = 0; r < 8; r++) {
        int idx = base + t + 256 * r;
        int i = idx >> 7, j = idx & 127;
        float outv = 0.f;
        if (mks[j] != 0.f) {
            float o  = __expf(Sp[idx]  - g_rmax[bh * 128 + i]) * g_rsum[bh * 128 + i];
            float in = __expf(Stp[idx] - g_cmax[bh * 128 + i]) * g_csum[bh * 128 + i];
            float val = (i == j) ? in : (o + in);
            outv = val * __expf(-lam * db[idx]);
        }
        mb[idx] = outv;
    }
}

// ============================================================
// node_hidden: msg tile staged in padded smem (conflict-free)
// ============================================================
#define NODEH_SMEM ((128 * 32 + 128 * 129) * 4)
__global__ void __launch_bounds__(256) nodeh_kernel()
{
    extern __shared__ float sm_[];
    float* vs = sm_;              // 128 x 32
    float* ms = sm_ + 128 * 32;   // 128 x 129 (padded)
    const int bh = blockIdx.x;
    const int b = bh >> 3, h = bh & 7;
    const int t = threadIdx.x;
    #pragma unroll
    for (int r = 0; r < 4; r++) {
        int idx4 = t + 256 * r;
        int n = idx4 >> 3;
        int c = (idx4 & 7) * 4;
        *(float4*)&vs[n * 32 + c] =
            *(const float4*)(g_v + (size_t)(b * 128 + n) * 256 + h * 32 + c);
    }
    #pragma unroll
    for (int r = 0; r < 16; r++) {
        int idx4 = t + 256 * r;                 // 4096 float4s
        int i = idx4 >> 5, j = (idx4 & 31) * 4;
        float4 v = *(const float4*)(g_msg + (size_t)bh * 16384 + i * 128 + j);
        float* d = ms + i * 129 + j;
        d[0] = v.x; d[1] = v.y; d[2] = v.z; d[3] = v.w;
    }
    __syncthreads();
    const int m = t & 127;
    const int dbase = (t >> 7) * 16;
    const float* mrow = ms + m * 129;
    float acc[16];
    #pragma unroll
    for (int d = 0; d < 16; d++) acc[d] = 0.f;
    for (int n = 0; n < 128; n++) {
        float w = mrow[n];
        const float* vr = &vs[n * 32 + dbase];
        #pragma unroll
        for (int d = 0; d < 16; d++) acc[d] = fmaf(w, vr[d], acc[d]);
    }
    float* outp = g_nodeh + (size_t)(b * 128 + m) * 256 + h * 32 + dbase;
    #pragma unroll
    for (int d = 0; d < 16; d++) outp[d] = acc[d];
}

// ============================================================
extern "C" void kernel_launch(void* const* d_in, const int* in_sizes, int n_in,
                              void* d_out, int out_size)
{
    const float* node = (const float*)d_in[0];
    const float* edge = (const float*)d_in[1];
    const float* dist = (const float*)d_in[2];
    const float* mask = (const float*)d_in[3];
    const float* lam  = (const float*)d_in[4];
    const float* Wq = (const float*)d_in[5];  const float* bq = (const float*)d_in[6];
    const float* Wk = (const float*)d_in[7];  const float* bk = (const float*)d_in[8];
    const float* Wv = (const float*)d_in[9];  const float* bv = (const float*)d_in[10];
    const float* Wn = (const float*)d_in[11]; const float* bn = (const float*)d_in[12];
    const float* We = (const float*)d_in[13]; const float* be = (const float*)d_in[14];

    float* out = (float*)d_out;
    float* node_out = out;
    float* edge_out = out + (size_t)NROWS_N * HID;

    float *pq, *pv, *pnh;
    __half *pk16, *pwk16, *pwe16;
    cudaGetSymbolAddress((void**)&pq, g_q);
    cudaGetSymbolAddress((void**)&pv, g_v);
    cudaGetSymbolAddress((void**)&pnh, g_nodeh);
    cudaGetSymbolAddress((void**)&pk16, g_k16);
    cudaGetSymbolAddress((void**)&pwk16, g_wk16);
    cudaGetSymbolAddress((void**)&pwe16, g_we16);

    cudaFuncSetAttribute((const void*)tgemm_kernel<true, false, true, false, true>,
                         cudaFuncAttributeMaxDynamicSharedMemorySize, TG_SMEM);
    cudaFuncSetAttribute((const void*)tgemm_kernel<false, true, false, true, false>,
                         cudaFuncAttributeMaxDynamicSharedMemorySize, TG_SMEM);
    cudaFuncSetAttribute((const void*)nodeh_kernel,
                         cudaFuncAttributeMaxDynamicSharedMemorySize, NODEH_SMEM);

    dim3 gT(2, NROWS_E / 64);           // (2 col blocks, 2048 row blocks)

    prep_w_kernel<<<256, 256>>>(Wk, We);
    gemm_qv_kernel<<<dim3(8, 8), 256>>>(node, Wq, bq, Wv, bv, pq, pv);
    tgemm_kernel<true, false, true, false, true><<<gT, 256, TG_SMEM>>>(edge, pwk16, bk, (void*)pk16);
    stats_kernel<<<2048, 256>>>(mask);
    message_kernel<<<dim3(64, 8), 256>>>(dist, mask, lam);
    tgemm_kernel<false, true, false, true, false><<<gT, 256, TG_SMEM>>>(pk16, pwe16, be, edge_out);
    nodeh_kernel<<<64, 256, NODEH_SMEM>>>();
    gemm_node_kernel<<<dim3(8, 4), 256>>>(pnh, Wn, bn, node_out);
}

// round 13
// speedup vs baseline: 1.1734x; 1.0266x over previous
#include <cuda_runtime.h>
#include <cuda_fp16.h>
#include <math.h>
#include <cstdint>

#define Bb 8
#define Mm 128
#define HID 256
#define NROWS_E (Bb*Mm*Mm)   // 131072
#define NROWS_N (Bb*Mm)      // 1024
#define QK_SCALE 0.17677669529663687f  // 1/sqrt(32)

// -------- scratch (device globals) --------
__device__ __align__(16) __half g_k16[(size_t)NROWS_E * HID];  // 67 MB fp16 k
__device__ float g_q[NROWS_N * HID];
__device__ float g_v[NROWS_N * HID];
__device__ float g_S[64 * 128 * 128];
__device__ float g_msg[64 * 128 * 128];
__device__ float g_nodeh[NROWS_N * HID];
__device__ __align__(16) __half g_wk16[HID * HID];
__device__ __align__(16) __half g_we16[HID * HID];

__device__ __forceinline__ float mish_f(float x) {
    if (x > 20.f) return x;
    float t = 1.f + __expf(x);
    float t2 = t * t;
    return x * __fdividef(t2 - 1.f, t2 + 1.f);
}

__device__ __forceinline__ uint32_t smem_u32(const void* p) {
    uint32_t a;
    asm("{ .reg .u64 t; cvta.to.shared.u64 t, %1; cvt.u32.u64 %0, t; }" : "=r"(a) : "l"(p));
    return a;
}
__device__ __forceinline__ void ldsm4(uint32_t* r, uint32_t addr) {
    asm volatile("ldmatrix.sync.aligned.m8n8.x4.shared.b16 {%0,%1,%2,%3}, [%4];"
        : "=r"(r[0]), "=r"(r[1]), "=r"(r[2]), "=r"(r[3]) : "r"(addr));
}
__device__ __forceinline__ void mma_f16(float* d, const uint32_t* a, const uint32_t* b) {
    asm volatile("mma.sync.aligned.m16n8k16.row.col.f32.f16.f16.f32 "
        "{%0,%1,%2,%3}, {%4,%5,%6,%7}, {%8,%9}, {%0,%1,%2,%3};"
        : "+f"(d[0]), "+f"(d[1]), "+f"(d[2]), "+f"(d[3])
        : "r"(a[0]), "r"(a[1]), "r"(a[2]), "r"(a[3]), "r"(b[0]), "r"(b[1]));
}
#define CP16(dst, src) asm volatile("cp.async.cg.shared.global [%0], [%1], 16;" :: "r"(dst), "l"(src))
#define CP_COMMIT() asm volatile("cp.async.commit_group;" ::: "memory")
#define CP_WAIT0()  asm volatile("cp.async.wait_group 0;" ::: "memory")
#define CP_WAIT1()  asm volatile("cp.async.wait_group 1;" ::: "memory")

// ============================================================
// prep: W fp32 -> fp16 (tiny)
// ============================================================
__global__ void __launch_bounds__(256) prep_w_kernel(const float* __restrict__ Wk,
                                                     const float* __restrict__ We)
{
    int t = blockIdx.x * 256 + threadIdx.x;    // 65536 W elements
    g_wk16[t] = __float2half_rn(Wk[t]);
    g_we16[t] = __float2half_rn(We[t]);
}

// ============================================================
// fp16 tensor GEMM: C[131072,256] = act(A' @ W^T + bias)
// AF32: A fp32 in gmem, converted on the fly (reg prefetch).
// MSG:  A scaled per (row, head=chunk) by g_msg, fused.
// SCORES: emit S[b,h,m,n] (coalesced only; no transpose).
// BM=64 BN=128 BK=32, 8 warps (warp tile 32x32), 3 CTAs/SM.
// ============================================================
#define ST_A    0
#define ST_B    5120
#define ST_MSG  15360
#define ST_SZ   15872
#define TG_SMEM (3 * ST_SZ)

template<bool AF32, bool MSG, bool OUT16, bool ACT, bool SCORES>
__global__ void __launch_bounds__(256, 3) tgemm_kernel(
    const void* __restrict__ Av, const __half* __restrict__ W,
    const float* __restrict__ bias, void* __restrict__ Cv)
{
    extern __shared__ char smem[];
    const uint32_t sb = smem_u32(smem);
    const int tid = threadIdx.x;
    const int wid = tid >> 5, lane = tid & 31;
    const int wm = wid >> 2, wn = wid & 3;      // warp tile rows wm*32, cols wn*32
    const int col0 = blockIdx.x * 128;
    const int r0 = blockIdx.y * 64;

    const __half* A16 = (const __half*)Av;
    const float*  A32 = (const float*)Av;

    int mb_base = 0;
    if (MSG) {
        int b = r0 >> 14, m = (r0 >> 7) & 127, n0 = r0 & 127;
        mb_base = b * 131072 + m * 128 + n0;    // + c*16384 per chunk
    }

    float acc[2][4][4];
    #pragma unroll
    for (int i = 0; i < 2; i++)
        #pragma unroll
        for (int j = 0; j < 4; j++)
            #pragma unroll
            for (int q = 0; q < 4; q++) acc[i][j][q] = 0.f;

    const uint32_t aA = sb + ST_A + (wm * 32 + (lane & 15)) * 80 + (lane >> 4) * 16;
    const uint32_t bA = sb + ST_B +
        (wn * 32 + ((lane >> 4) & 1) * 8 + (lane & 7)) * 80 + ((lane >> 3) & 1) * 16;

    const int arow = tid >> 2, aq = tid & 3;    // A: 64 rows x 4 chunks

    auto fill = [&](int c, int stg) {
        uint32_t base = sb + stg * ST_SZ;
        if (!AF32)
            CP16(base + ST_A + (uint32_t)(arow * 80 + aq * 16),
                 (const char*)(A16 + (((size_t)(r0 + arow)) << 8) + c * 32 + aq * 8));
        #pragma unroll
        for (int u = 0; u < 2; u++) {
            int idx = tid + 256 * u;            // B: 128 rows x 4 chunks = 512
            int row = idx >> 2, q = idx & 3;
            CP16(base + ST_B + (uint32_t)(row * 80 + q * 16),
                 (const char*)(W + (((size_t)(col0 + row)) << 8) + c * 32 + q * 8));
        }
        if (MSG && tid < 16)
            CP16(base + ST_MSG + (uint32_t)(tid * 16),
                 (const char*)(g_msg + mb_base + c * 16384 + tid * 4));
        CP_COMMIT();
    };
    auto ldA = [&](int c, float4& f0, float4& f1) {
        const float* p = A32 + (((size_t)(r0 + arow)) << 8) + c * 32 + aq * 8;
        f0 = *(const float4*)p;
        f1 = *(const float4*)(p + 4);
    };
    auto cvtstA = [&](int stg, const float4& f0, const float4& f1) {
        union { __half2 h[4]; uint4 u; } o;
        o.h[0] = __floats2half2_rn(f0.x, f0.y);
        o.h[1] = __floats2half2_rn(f0.z, f0.w);
        o.h[2] = __floats2half2_rn(f1.x, f1.y);
        o.h[3] = __floats2half2_rn(f1.z, f1.w);
        *(uint4*)(smem + stg * ST_SZ + ST_A + arow * 80 + aq * 16) = o.u;
    };

    float4 pa0, pa1;
    if (AF32) {
        ldA(0, pa0, pa1); cvtstA(0, pa0, pa1);
        ldA(1, pa0, pa1); cvtstA(1, pa0, pa1);
        ldA(2, pa0, pa1);                 // prefetch chunk 2
    }
    fill(0, 0);
    fill(1, 1);
    #pragma unroll 1
    for (int c = 0; c < 8; c++) {
        if (c < 7) CP_WAIT1(); else CP_WAIT0();
        __syncthreads();
        if (c < 6) {
            fill(c + 2, (c + 2) % 3);
            if (AF32) {
                cvtstA((c + 2) % 3, pa0, pa1);     // store chunk c+2
                if (c < 5) ldA(c + 3, pa0, pa1);   // prefetch chunk c+3
            }
        }
        const uint32_t soff = (uint32_t)((c % 3) * ST_SZ);

        // msg scales for this chunk (head == c).
        // mma m16n8k16 A-fragment: regs {a0,a2} hold row g=lane>>2,
        // regs {a1,a3} hold row g+8 (within each 16-row tile).
        __half2 s00, s01, s10, s11;
        if (MSG) {
            const float* sp = (const float*)(smem + (c % 3) * ST_SZ + ST_MSG);
            int g = lane >> 2;
            s00 = __half2half2(__float2half_rn(sp[wm * 32 + g]));
            s01 = __half2half2(__float2half_rn(sp[wm * 32 + g + 8]));
            s10 = __half2half2(__float2half_rn(sp[wm * 32 + 16 + g]));
            s11 = __half2half2(__float2half_rn(sp[wm * 32 + 16 + g + 8]));
        }

        const uint32_t ab = aA + soff;
        const uint32_t bb = bA + soff;
        #pragma unroll
        for (int ks = 0; ks < 2; ks++) {
            const uint32_t koff = ks * 32;
            uint32_t ah[8], bf[8];
            ldsm4(&ah[0], ab + koff);
            ldsm4(&ah[4], ab + 16 * 80 + koff);
            ldsm4(&bf[0], bb + koff);
            ldsm4(&bf[4], bb + 16 * 80 + koff);
            if (MSG) {
                __half2* h = reinterpret_cast<__half2*>(ah);
                h[0] = __hmul2(h[0], s00); h[2] = __hmul2(h[2], s00);
                h[1] = __hmul2(h[1], s01); h[3] = __hmul2(h[3], s01);
                h[4] = __hmul2(h[4], s10); h[6] = __hmul2(h[6], s10);
                h[5] = __hmul2(h[5], s11); h[7] = __hmul2(h[7], s11);
            }
            #pragma unroll
            for (int mt = 0; mt < 2; mt++)
                #pragma unroll
                for (int nt = 0; nt < 4; nt++)
                    mma_f16(acc[mt][nt], &ah[mt * 4], &bf[(nt >> 1) * 4 + (nt & 1) * 2]);
        }
    }

    // q values for fused scores (warp's 32 cols = head bx*4+wn)
    float qv[4][2];
    float dotR[4] = {0.f, 0.f, 0.f, 0.f};
    if (SCORES) {
        int b = r0 >> 14, m = (r0 >> 7) & 127;
        const float* qrow = g_q + (size_t)(b * 128 + m) * 256 + col0 + wn * 32 + (lane & 3) * 2;
        #pragma unroll
        for (int nt = 0; nt < 4; nt++) { qv[nt][0] = qrow[nt * 8]; qv[nt][1] = qrow[nt * 8 + 1]; }
    }

    // epilogue
    #pragma unroll
    for (int nt = 0; nt < 4; nt++) {
        const int col = col0 + wn * 32 + nt * 8 + (lane & 3) * 2;
        const float b0 = bias[col], b1 = bias[col + 1];
        #pragma unroll
        for (int mt = 0; mt < 2; mt++) {
            int row = r0 + wm * 32 + mt * 16 + (lane >> 2);
            float v0 = acc[mt][nt][0] + b0, v1 = acc[mt][nt][1] + b1;
            float v2 = acc[mt][nt][2] + b0, v3 = acc[mt][nt][3] + b1;
            if (SCORES) {
                dotR[2 * mt]     += v0 * qv[nt][0] + v1 * qv[nt][1];
                dotR[2 * mt + 1] += v2 * qv[nt][0] + v3 * qv[nt][1];
            }
            if (ACT) { v0 = mish_f(v0); v1 = mish_f(v1); v2 = mish_f(v2); v3 = mish_f(v3); }
            if (OUT16) {
                __half* C = (__half*)Cv;
                *(__half2*)(C + (size_t)row * 256 + col) = __floats2half2_rn(v0, v1);
                *(__half2*)(C + (size_t)(row + 8) * 256 + col) = __floats2half2_rn(v2, v3);
            } else {
                float* C = (float*)Cv;
                float2 p0; p0.x = v0; p0.y = v1;
                float2 p1; p1.x = v2; p1.y = v3;
                *(float2*)(C + (size_t)row * 256 + col) = p0;
                *(float2*)(C + (size_t)(row + 8) * 256 + col) = p1;
            }
        }
    }

    if (SCORES) {
        #pragma unroll
        for (int i = 0; i < 4; i++) {
            dotR[i] += __shfl_xor_sync(0xffffffffu, dotR[i], 1);
            dotR[i] += __shfl_xor_sync(0xffffffffu, dotR[i], 2);
        }
        if ((lane & 3) == 0) {
            int b = r0 >> 14, m = (r0 >> 7) & 127, n0 = r0 & 127;
            int h = blockIdx.x * 4 + wn;
            int g = lane >> 2;
            float* Sp = g_S + (((size_t)(b * 8 + h) * 128) + m) * 128 + n0 + wm * 32;
            Sp[g]      = dotR[0] * QK_SCALE;
            Sp[g + 8]  = dotR[1] * QK_SCALE;
            Sp[g + 16] = dotR[2] * QK_SCALE;
            Sp[g + 24] = dotR[3] * QK_SCALE;
        }
    }
}

// ============================================================
// fp32 SGEMM core for the small (1024-row) projections
// ============================================================
template<bool ACT>
__device__ __forceinline__ void gemm_core(
    const float* __restrict__ A, const float* __restrict__ W,
    const float* __restrict__ bias, float* __restrict__ C,
    int row0, int col0)
{
    __shared__ __align__(16) float As[16][132];
    __shared__ __align__(16) float Bs[16][68];

    const int t  = threadIdx.x;
    const int tx = t & 15;
    const int ty = t >> 4;
    const int lr = t >> 2;
    const int lc = (t & 3) << 2;
    const int gr1 = row0 + lr;
    const int gr2 = gr1 + 64;

    float acc[8][4];
    #pragma unroll
    for (int i = 0; i < 8; i++)
        #pragma unroll
        for (int j = 0; j < 4; j++) acc[i][j] = 0.f;

    for (int k0 = 0; k0 < HID; k0 += 16) {
        float4 a1 = *(const float4*)(A + (size_t)gr1 * HID + k0 + lc);
        float4 a2 = *(const float4*)(A + (size_t)gr2 * HID + k0 + lc);
        As[lc + 0][lr] = a1.x; As[lc + 1][lr] = a1.y;
        As[lc + 2][lr] = a1.z; As[lc + 3][lr] = a1.w;
        As[lc + 0][lr + 64] = a2.x; As[lc + 1][lr + 64] = a2.y;
        As[lc + 2][lr + 64] = a2.z; As[lc + 3][lr + 64] = a2.w;
        float4 b4 = *(const float4*)(W + (size_t)(col0 + lr) * HID + k0 + lc);
        Bs[lc + 0][lr] = b4.x; Bs[lc + 1][lr] = b4.y;
        Bs[lc + 2][lr] = b4.z; Bs[lc + 3][lr] = b4.w;
        __syncthreads();
        #pragma unroll
        for (int kk = 0; kk < 16; kk++) {
            float4 alo = *(const float4*)&As[kk][ty * 8];
            float4 ahi = *(const float4*)&As[kk][ty * 8 + 4];
            float4 bv  = *(const float4*)&Bs[kk][tx * 4];
            float avv[8] = {alo.x, alo.y, alo.z, alo.w, ahi.x, ahi.y, ahi.z, ahi.w};
            float bw[4] = {bv.x, bv.y, bv.z, bv.w};
            #pragma unroll
            for (int i = 0; i < 8; i++)
                #pragma unroll
                for (int j = 0; j < 4; j++)
                    acc[i][j] = fmaf(avv[i], bw[j], acc[i][j]);
        }
        __syncthreads();
    }

    float4 bb = *(const float4*)(bias + col0 + tx * 4);
    float bias4[4] = {bb.x, bb.y, bb.z, bb.w};
    #pragma unroll
    for (int i = 0; i < 8; i++) {
        float v0 = acc[i][0] + bias4[0];
        float v1 = acc[i][1] + bias4[1];
        float v2 = acc[i][2] + bias4[2];
        float v3 = acc[i][3] + bias4[3];
        if (ACT) { v0 = mish_f(v0); v1 = mish_f(v1); v2 = mish_f(v2); v3 = mish_f(v3); }
        float4 o; o.x = v0; o.y = v1; o.z = v2; o.w = v3;
        *(float4*)(C + (size_t)(row0 + ty * 8 + i) * HID + col0 + tx * 4) = o;
    }
}

__global__ void __launch_bounds__(256)
gemm_qv_kernel(const float* __restrict__ node,
               const float* __restrict__ Wq, const float* __restrict__ bq,
               const float* __restrict__ Wv, const float* __restrict__ bv,
               float* __restrict__ Cq, float* __restrict__ Cv)
{
    int by = blockIdx.y;
    if (by < 4) gemm_core<false>(node, Wq, bq, Cq, blockIdx.x * 128, by * 64);
    else        gemm_core<false>(node, Wv, bv, Cv, blockIdx.x * 128, (by - 4) * 64);
}

__global__ void __launch_bounds__(256)
gemm_node_kernel(const float* __restrict__ A, const float* __restrict__ W,
                 const float* __restrict__ bias, float* __restrict__ C)
{
    gemm_core<true>(A, W, bias, C, blockIdx.x * 128, blockIdx.y * 64);
}

// ============================================================
// Fused softmax stats + message per (bh, 16-row tile).
// Loads S rows coalesced + S column-slab (transposed in smem),
// computes row stats, col stats, then the 16x128 msg tile.
// ============================================================
__global__ void __launch_bounds__(256) softmsg_kernel(
    const float* __restrict__ dist, const float* __restrict__ mask,
    const float* __restrict__ lamp)
{
    __shared__ __align__(16) float rowS[16][128];
    __shared__ float colT[128][17];
    __shared__ float mks[128];
    __shared__ float rm[16], rs[16], cm[16], cs[16];

    const int bh = blockIdx.x, b = bh >> 3;
    const int i0 = blockIdx.y * 16;
    const int t = threadIdx.x;
    const int w = t >> 5, lane = t & 31;
    const float lam = lamp[0];
    const float* Sg = g_S + (size_t)bh * 16384;

    if (t < 128) mks[t] = mask[b * 128 + t];

    // rows: S[i0+ii, :], 2048 floats = 512 float4, 2 per thread
    #pragma unroll
    for (int r = 0; r < 2; r++) {
        int idx4 = t + 256 * r;
        int ii = idx4 >> 5, j = (idx4 & 31) * 4;
        *(float4*)&rowS[ii][j] = *(const float4*)(Sg + (i0 + ii) * 128 + j);
    }
    // column slab: colT[j][ii] = S[j, i0+ii]; 128 rows x 4 float4
    #pragma unroll
    for (int r = 0; r < 2; r++) {
        int idx4 = t + 256 * r;
        int j = idx4 >> 2, c = (idx4 & 3) * 4;
        float4 v = *(const float4*)(Sg + j * 128 + i0 + c);
        colT[j][c] = v.x; colT[j][c + 1] = v.y;
        colT[j][c + 2] = v.z; colT[j][c + 3] = v.w;
    }
    __syncthreads();

    // warp w: rows 2w, 2w+1 and cols 2w, 2w+1 of the tile
    #pragma unroll
    for (int u = 0; u < 2; u++) {
        int ii = 2 * w + u;
        // row stats over j (masked)
        float mx = -1e30f;
        #pragma unroll
        for (int k = 0; k < 4; k++) {
            int j = lane + 32 * k;
            if (mks[j] != 0.f) mx = fmaxf(mx, rowS[ii][j]);
        }
        #pragma unroll
        for (int s = 16; s > 0; s >>= 1) mx = fmaxf(mx, __shfl_xor_sync(0xffffffffu, mx, s));
        float sm = 0.f;
        #pragma unroll
        for (int k = 0; k < 4; k++) {
            int j = lane + 32 * k;
            if (mks[j] != 0.f) sm += __expf(rowS[ii][j] - mx);
        }
        #pragma unroll
        for (int s = 16; s > 0; s >>= 1) sm += __shfl_xor_sync(0xffffffffu, sm, s);
        if (lane == 0) { rm[ii] = mx; rs[ii] = 1.f / sm; }

        // col stats over j (masked): colT[j][ii]
        float cmx = -1e30f;
        #pragma unroll
        for (int k = 0; k < 4; k++) {
            int j = lane + 32 * k;
            if (mks[j] != 0.f) cmx = fmaxf(cmx, colT[j][ii]);
        }
        #pragma unroll
        for (int s = 16; s > 0; s >>= 1) cmx = fmaxf(cmx, __shfl_xor_sync(0xffffffffu, cmx, s));
        float csm = 0.f;
        #pragma unroll
        for (int k = 0; k < 4; k++) {
            int j = lane + 32 * k;
            if (mks[j] != 0.f) csm += __expf(colT[j][ii] - cmx);
        }
        #pragma unroll
        for (int s = 16; s > 0; s >>= 1) csm += __shfl_xor_sync(0xffffffffu, csm, s);
        if (lane == 0) { cm[ii] = cmx; cs[ii] = 1.f / csm; }
    }
    __syncthreads();

    const float* db = dist + (size_t)b * 16384 + i0 * 128;
    float* mb = g_msg + (size_t)bh * 16384 + i0 * 128;
    #pragma unroll
    for (int r = 0; r < 8; r++) {
        int idx = t + 256 * r;          // 0..2047
        int ii = idx >> 7, j = idx & 127;
        float outv = 0.f;
        if (mks[j] != 0.f) {
            float o  = __expf(rowS[ii][j] - rm[ii]) * rs[ii];
            float in = __expf(colT[j][ii] - cm[ii]) * cs[ii];
            float val = ((i0 + ii) == j) ? in : (o + in);
            outv = val * __expf(-lam * db[idx]);
        }
        mb[idx] = outv;
    }
}

// ============================================================
// node_hidden: msg tile staged in padded smem (conflict-free)
// ============================================================
#define NODEH_SMEM ((128 * 32 + 128 * 129) * 4)
__global__ void __launch_bounds__(256) nodeh_kernel()
{
    extern __shared__ float sm_[];
    float* vs = sm_;              // 128 x 32
    float* ms = sm_ + 128 * 32;   // 128 x 129 (padded)
    const int bh = blockIdx.x;
    const int b = bh >> 3, h = bh & 7;
    const int t = threadIdx.x;
    #pragma unroll
    for (int r = 0; r < 4; r++) {
        int idx4 = t + 256 * r;
        int n = idx4 >> 3;
        int c = (idx4 & 7) * 4;
        *(float4*)&vs[n * 32 + c] =
            *(const float4*)(g_v + (size_t)(b * 128 + n) * 256 + h * 32 + c);
    }
    #pragma unroll
    for (int r = 0; r < 16; r++) {
        int idx4 = t + 256 * r;                 // 4096 float4s
        int i = idx4 >> 5, j = (idx4 & 31) * 4;
        float4 v = *(const float4*)(g_msg + (size_t)bh * 16384 + i * 128 + j);
        float* d = ms + i * 129 + j;
        d[0] = v.x; d[1] = v.y; d[2] = v.z; d[3] = v.w;
    }
    __syncthreads();
    const int m = t & 127;
    const int dbase = (t >> 7) * 16;
    const float* mrow = ms + m * 129;
    float acc[16];
    #pragma unroll
    for (int d = 0; d < 16; d++) acc[d] = 0.f;
    for (int n = 0; n < 128; n++) {
        float w = mrow[n];
        const float* vr = &vs[n * 32 + dbase];
        #pragma unroll
        for (int d = 0; d < 16; d++) acc[d] = fmaf(w, vr[d], acc[d]);
    }
    float* outp = g_nodeh + (size_t)(b * 128 + m) * 256 + h * 32 + dbase;
    #pragma unroll
    for (int d = 0; d < 16; d++) outp[d] = acc[d];
}

// ============================================================
extern "C" void kernel_launch(void* const* d_in, const int* in_sizes, int n_in,
                              void* d_out, int out_size)
{
    const float* node = (const float*)d_in[0];
    const float* edge = (const float*)d_in[1];
    const float* dist = (const float*)d_in[2];
    const float* mask = (const float*)d_in[3];
    const float* lam  = (const float*)d_in[4];
    const float* Wq = (const float*)d_in[5];  const float* bq = (const float*)d_in[6];
    const float* Wk = (const float*)d_in[7];  const float* bk = (const float*)d_in[8];
    const float* Wv = (const float*)d_in[9];  const float* bv = (const float*)d_in[10];
    const float* Wn = (const float*)d_in[11]; const float* bn = (const float*)d_in[12];
    const float* We = (const float*)d_in[13]; const float* be = (const float*)d_in[14];

    float* out = (float*)d_out;
    float* node_out = out;
    float* edge_out = out + (size_t)NROWS_N * HID;

    float *pq, *pv, *pnh;
    __half *pk16, *pwk16, *pwe16;
    cudaGetSymbolAddress((void**)&pq, g_q);
    cudaGetSymbolAddress((void**)&pv, g_v);
    cudaGetSymbolAddress((void**)&pnh, g_nodeh);
    cudaGetSymbolAddress((void**)&pk16, g_k16);
    cudaGetSymbolAddress((void**)&pwk16, g_wk16);
    cudaGetSymbolAddress((void**)&pwe16, g_we16);

    cudaFuncSetAttribute((const void*)tgemm_kernel<true, false, true, false, true>,
                         cudaFuncAttributeMaxDynamicSharedMemorySize, TG_SMEM);
    cudaFuncSetAttribute((const void*)tgemm_kernel<false, true, false, true, false>,
                         cudaFuncAttributeMaxDynamicSharedMemorySize, TG_SMEM);
    cudaFuncSetAttribute((const void*)nodeh_kernel,
                         cudaFuncAttributeMaxDynamicSharedMemorySize, NODEH_SMEM);

    dim3 gT(2, NROWS_E / 64);           // (2 col blocks, 2048 row blocks)

    prep_w_kernel<<<256, 256>>>(Wk, We);
    gemm_qv_kernel<<<dim3(8, 8), 256>>>(node, Wq, bq, Wv, bv, pq, pv);
    tgemm_kernel<true, false, true, false, true><<<gT, 256, TG_SMEM>>>(edge, pwk16, bk, (void*)pk16);
    softmsg_kernel<<<dim3(64, 8), 256>>>(dist, mask, lam);
    tgemm_kernel<false, true, false, true, false><<<gT, 256, TG_SMEM>>>(pk16, pwe16, be, edge_out);
    nodeh_kernel<<<64, 256, NODEH_SMEM>>>();
    gemm_node_kernel<<<dim3(8, 4), 256>>>(pnh, Wn, bn, node_out);
}

// round 14
// speedup vs baseline: 1.2479x; 1.0635x over previous
#include <cuda_runtime.h>
#include <cuda_fp16.h>
#include <math.h>
#include <cstdint>

#define Bb 8
#define Mm 128
#define HID 256
#define NROWS_E (Bb*Mm*Mm)   // 131072
#define NROWS_N (Bb*Mm)      // 1024
#define QK_SCALE 0.17677669529663687f  // 1/sqrt(32)

// -------- scratch (device globals) --------
__device__ __align__(16) __half g_k16[(size_t)NROWS_E * HID];  // 67 MB fp16 k
__device__ float g_q[NROWS_N * HID];
__device__ float g_v[NROWS_N * HID];
__device__ float g_S[64 * 128 * 128];
__device__ float g_msg[64 * 128 * 128];
__device__ float g_nodeh[NROWS_N * HID];
__device__ __align__(16) __half g_wk16[HID * HID];
__device__ __align__(16) __half g_we16[HID * HID];

__device__ __forceinline__ float mish_f(float x) {
    if (x > 20.f) return x;
    float t = 1.f + __expf(x);
    float t2 = t * t;
    return x * __fdividef(t2 - 1.f, t2 + 1.f);
}

__device__ __forceinline__ uint32_t smem_u32(const void* p) {
    uint32_t a;
    asm("{ .reg .u64 t; cvta.to.shared.u64 t, %1; cvt.u32.u64 %0, t; }" : "=r"(a) : "l"(p));
    return a;
}
__device__ __forceinline__ void ldsm4(uint32_t* r, uint32_t addr) {
    asm volatile("ldmatrix.sync.aligned.m8n8.x4.shared.b16 {%0,%1,%2,%3}, [%4];"
        : "=r"(r[0]), "=r"(r[1]), "=r"(r[2]), "=r"(r[3]) : "r"(addr));
}
__device__ __forceinline__ void mma_f16(float* d, const uint32_t* a, const uint32_t* b) {
    asm volatile("mma.sync.aligned.m16n8k16.row.col.f32.f16.f16.f32 "
        "{%0,%1,%2,%3}, {%4,%5,%6,%7}, {%8,%9}, {%0,%1,%2,%3};"
        : "+f"(d[0]), "+f"(d[1]), "+f"(d[2]), "+f"(d[3])
        : "r"(a[0]), "r"(a[1]), "r"(a[2]), "r"(a[3]), "r"(b[0]), "r"(b[1]));
}
#define CP16(dst, src) asm volatile("cp.async.cg.shared.global [%0], [%1], 16;" :: "r"(dst), "l"(src))
#define CP_COMMIT() asm volatile("cp.async.commit_group;" ::: "memory")
#define CP_WAIT0()  asm volatile("cp.async.wait_group 0;" ::: "memory")

// ============================================================
// fp16 tensor GEMM: C[131072,256] = act(A' @ W^T + bias)
// AF32: A fp32 in gmem, converted on the fly (reg prefetch).
// MSG:  A scaled per (row, head) by g_msg, fused (head = 2c + ks/2).
// SCORES: emit S[b,h,m,n] from the fp32 accumulators.
// BM=64 BN=128 BK=64, 8 warps (warp tile 32x32), 2-stage pipe,
// 3 CTAs/SM, 4 chunks => 4 barriers per CTA.
// ============================================================
#define ST_A    0
#define ST_B    9216
#define ST_MSG  27648
#define ST_SZ   28160
#define TG_SMEM (2 * ST_SZ)

template<bool AF32, bool MSG, bool OUT16, bool ACT, bool SCORES>
__global__ void __launch_bounds__(256, 3) tgemm_kernel(
    const void* __restrict__ Av, const __half* __restrict__ W,
    const float* __restrict__ bias, void* __restrict__ Cv)
{
    extern __shared__ char smem[];
    const uint32_t sb = smem_u32(smem);
    const int tid = threadIdx.x;
    const int wid = tid >> 5, lane = tid & 31;
    const int wm = wid >> 2, wn = wid & 3;      // warp tile rows wm*32, cols wn*32
    const int col0 = blockIdx.x * 128;
    const int r0 = blockIdx.y * 64;

    const __half* A16 = (const __half*)Av;
    const float*  A32 = (const float*)Av;

    int mb_base = 0;
    if (MSG) {
        int b = r0 >> 14, m = (r0 >> 7) & 127, n0 = r0 & 127;
        mb_base = b * 131072 + m * 128 + n0;    // + head*16384
    }

    float acc[2][4][4];
    #pragma unroll
    for (int i = 0; i < 2; i++)
        #pragma unroll
        for (int j = 0; j < 4; j++)
            #pragma unroll
            for (int q = 0; q < 4; q++) acc[i][j][q] = 0.f;

    const uint32_t aA = sb + ST_A + (wm * 32 + (lane & 15)) * 144 + (lane >> 4) * 16;
    const uint32_t bA = sb + ST_B +
        (wn * 32 + ((lane >> 4) & 1) * 8 + (lane & 7)) * 144 + ((lane >> 3) & 1) * 16;

    auto fillB = [&](int c, int stg) {
        uint32_t base = sb + stg * ST_SZ;
        if (!AF32) {
            #pragma unroll
            for (int u = 0; u < 2; u++) {
                int idx = tid + 256 * u;        // A: 64 rows x 8 chunks = 512
                int row = idx >> 3, q = idx & 7;
                CP16(base + ST_A + (uint32_t)(row * 144 + q * 16),
                     (const char*)(A16 + (((size_t)(r0 + row)) << 8) + c * 64 + q * 8));
            }
        }
        #pragma unroll
        for (int u = 0; u < 4; u++) {
            int idx = tid + 256 * u;            // B: 128 rows x 8 chunks = 1024
            int row = idx >> 3, q = idx & 7;
            CP16(base + ST_B + (uint32_t)(row * 144 + q * 16),
                 (const char*)(W + (((size_t)(col0 + row)) << 8) + c * 64 + q * 8));
        }
        if (MSG && tid < 32) {                  // 2 heads x 64 floats = 512B
            int d = tid >> 4, q = tid & 15;
            CP16(base + ST_MSG + (uint32_t)(d * 256 + q * 16),
                 (const char*)(g_msg + mb_base + (2 * c + d) * 16384 + q * 4));
        }
        CP_COMMIT();
    };
    auto ldcvtA = [&](int c, uint4* h) {
        #pragma unroll
        for (int u = 0; u < 2; u++) {
            int idx = tid + 256 * u;
            int row = idx >> 3, q = idx & 7;
            const float* p = A32 + (((size_t)(r0 + row)) << 8) + c * 64 + q * 8;
            float4 f0 = *(const float4*)p;
            float4 f1 = *(const float4*)(p + 4);
            union { __half2 hh[4]; uint4 u4; } o;
            o.hh[0] = __floats2half2_rn(f0.x, f0.y);
            o.hh[1] = __floats2half2_rn(f0.z, f0.w);
            o.hh[2] = __floats2half2_rn(f1.x, f1.y);
            o.hh[3] = __floats2half2_rn(f1.z, f1.w);
            h[u] = o.u4;
        }
    };
    auto stA = [&](int stg, const uint4* h) {
        #pragma unroll
        for (int u = 0; u < 2; u++) {
            int idx = tid + 256 * u;
            int row = idx >> 3, q = idx & 7;
            *(uint4*)(smem + stg * ST_SZ + ST_A + row * 144 + q * 16) = h[u];
        }
    };

    uint4 held[2];
    if (AF32) {
        uint4 tmp[2];
        ldcvtA(0, tmp); stA(0, tmp);
        ldcvtA(1, held);
    }
    fillB(0, 0);
    #pragma unroll 1
    for (int c = 0; c < 4; c++) {
        CP_WAIT0();
        __syncthreads();
        if (c < 3) {
            fillB(c + 1, (c + 1) & 1);
            if (AF32) {
                stA((c + 1) & 1, held);
                if (c < 2) ldcvtA(c + 2, held);
            }
        }
        const uint32_t soff = (uint32_t)((c & 1) * ST_SZ);
        const uint32_t ab = aA + soff;
        const uint32_t bb = bA + soff;
        #pragma unroll
        for (int ks = 0; ks < 4; ks++) {
            const uint32_t koff = ks * 32;
            // msg scales: head = 2c + (ks>>1); A-fragment rows:
            // {a0,a2} row g=lane>>2, {a1,a3} row g+8 per 16-row tile.
            __half2 s00, s01, s10, s11;
            if (MSG) {
                const float* sp = (const float*)(smem + (c & 1) * ST_SZ + ST_MSG + (ks >> 1) * 256);
                int g = lane >> 2;
                s00 = __half2half2(__float2half_rn(sp[wm * 32 + g]));
                s01 = __half2half2(__float2half_rn(sp[wm * 32 + g + 8]));
                s10 = __half2half2(__float2half_rn(sp[wm * 32 + 16 + g]));
                s11 = __half2half2(__float2half_rn(sp[wm * 32 + 16 + g + 8]));
            }
            uint32_t ah[8], bf[8];
            ldsm4(&ah[0], ab + koff);
            ldsm4(&ah[4], ab + 16 * 144 + koff);
            ldsm4(&bf[0], bb + koff);
            ldsm4(&bf[4], bb + 16 * 144 + koff);
            if (MSG) {
                __half2* h = reinterpret_cast<__half2*>(ah);
                h[0] = __hmul2(h[0], s00); h[2] = __hmul2(h[2], s00);
                h[1] = __hmul2(h[1], s01); h[3] = __hmul2(h[3], s01);
                h[4] = __hmul2(h[4], s10); h[6] = __hmul2(h[6], s10);
                h[5] = __hmul2(h[5], s11); h[7] = __hmul2(h[7], s11);
            }
            #pragma unroll
            for (int mt = 0; mt < 2; mt++)
                #pragma unroll
                for (int nt = 0; nt < 4; nt++)
                    mma_f16(acc[mt][nt], &ah[mt * 4], &bf[(nt >> 1) * 4 + (nt & 1) * 2]);
        }
    }

    // q values for fused scores (warp's 32 cols = head bx*4+wn)
    float qv[4][2];
    float dotR[4] = {0.f, 0.f, 0.f, 0.f};
    if (SCORES) {
        int b = r0 >> 14, m = (r0 >> 7) & 127;
        const float* qrow = g_q + (size_t)(b * 128 + m) * 256 + col0 + wn * 32 + (lane & 3) * 2;
        #pragma unroll
        for (int nt = 0; nt < 4; nt++) { qv[nt][0] = qrow[nt * 8]; qv[nt][1] = qrow[nt * 8 + 1]; }
    }

    // epilogue
    #pragma unroll
    for (int nt = 0; nt < 4; nt++) {
        const int col = col0 + wn * 32 + nt * 8 + (lane & 3) * 2;
        const float b0 = bias[col], b1 = bias[col + 1];
        #pragma unroll
        for (int mt = 0; mt < 2; mt++) {
            int row = r0 + wm * 32 + mt * 16 + (lane >> 2);
            float v0 = acc[mt][nt][0] + b0, v1 = acc[mt][nt][1] + b1;
            float v2 = acc[mt][nt][2] + b0, v3 = acc[mt][nt][3] + b1;
            if (SCORES) {
                dotR[2 * mt]     += v0 * qv[nt][0] + v1 * qv[nt][1];
                dotR[2 * mt + 1] += v2 * qv[nt][0] + v3 * qv[nt][1];
            }
            if (ACT) { v0 = mish_f(v0); v1 = mish_f(v1); v2 = mish_f(v2); v3 = mish_f(v3); }
            if (OUT16) {
                __half* C = (__half*)Cv;
                *(__half2*)(C + (size_t)row * 256 + col) = __floats2half2_rn(v0, v1);
                *(__half2*)(C + (size_t)(row + 8) * 256 + col) = __floats2half2_rn(v2, v3);
            } else {
                float* C = (float*)Cv;
                float2 p0; p0.x = v0; p0.y = v1;
                float2 p1; p1.x = v2; p1.y = v3;
                *(float2*)(C + (size_t)row * 256 + col) = p0;
                *(float2*)(C + (size_t)(row + 8) * 256 + col) = p1;
            }
        }
    }

    if (SCORES) {
        #pragma unroll
        for (int i = 0; i < 4; i++) {
            dotR[i] += __shfl_xor_sync(0xffffffffu, dotR[i], 1);
            dotR[i] += __shfl_xor_sync(0xffffffffu, dotR[i], 2);
        }
        if ((lane & 3) == 0) {
            int b = r0 >> 14, m = (r0 >> 7) & 127, n0 = r0 & 127;
            int h = blockIdx.x * 4 + wn;
            int g = lane >> 2;
            float* Sp = g_S + (((size_t)(b * 8 + h) * 128) + m) * 128 + n0 + wm * 32;
            Sp[g]      = dotR[0] * QK_SCALE;
            Sp[g + 8]  = dotR[1] * QK_SCALE;
            Sp[g + 16] = dotR[2] * QK_SCALE;
            Sp[g + 24] = dotR[3] * QK_SCALE;
        }
    }
}

// ============================================================
// fp32 SGEMM core for the small (1024-row) projections
// ============================================================
template<bool ACT>
__device__ __forceinline__ void gemm_core(
    const float* __restrict__ A, const float* __restrict__ W,
    const float* __restrict__ bias, float* __restrict__ C,
    int row0, int col0)
{
    __shared__ __align__(16) float As[16][132];
    __shared__ __align__(16) float Bs[16][68];

    const int t  = threadIdx.x;
    const int tx = t & 15;
    const int ty = t >> 4;
    const int lr = t >> 2;
    const int lc = (t & 3) << 2;
    const int gr1 = row0 + lr;
    const int gr2 = gr1 + 64;

    float acc[8][4];
    #pragma unroll
    for (int i = 0; i < 8; i++)
        #pragma unroll
        for (int j = 0; j < 4; j++) acc[i][j] = 0.f;

    for (int k0 = 0; k0 < HID; k0 += 16) {
        float4 a1 = *(const float4*)(A + (size_t)gr1 * HID + k0 + lc);
        float4 a2 = *(const float4*)(A + (size_t)gr2 * HID + k0 + lc);
        As[lc + 0][lr] = a1.x; As[lc + 1][lr] = a1.y;
        As[lc + 2][lr] = a1.z; As[lc + 3][lr] = a1.w;
        As[lc + 0][lr + 64] = a2.x; As[lc + 1][lr + 64] = a2.y;
        As[lc + 2][lr + 64] = a2.z; As[lc + 3][lr + 64] = a2.w;
        float4 b4 = *(const float4*)(W + (size_t)(col0 + lr) * HID + k0 + lc);
        Bs[lc + 0][lr] = b4.x; Bs[lc + 1][lr] = b4.y;
        Bs[lc + 2][lr] = b4.z; Bs[lc + 3][lr] = b4.w;
        __syncthreads();
        #pragma unroll
        for (int kk = 0; kk < 16; kk++) {
            float4 alo = *(const float4*)&As[kk][ty * 8];
            float4 ahi = *(const float4*)&As[kk][ty * 8 + 4];
            float4 bv  = *(const float4*)&Bs[kk][tx * 4];
            float avv[8] = {alo.x, alo.y, alo.z, alo.w, ahi.x, ahi.y, ahi.z, ahi.w};
            float bw[4] = {bv.x, bv.y, bv.z, bv.w};
            #pragma unroll
            for (int i = 0; i < 8; i++)
                #pragma unroll
                for (int j = 0; j < 4; j++)
                    acc[i][j] = fmaf(avv[i], bw[j], acc[i][j]);
        }
        __syncthreads();
    }

    float4 bb = *(const float4*)(bias + col0 + tx * 4);
    float bias4[4] = {bb.x, bb.y, bb.z, bb.w};
    #pragma unroll
    for (int i = 0; i < 8; i++) {
        float v0 = acc[i][0] + bias4[0];
        float v1 = acc[i][1] + bias4[1];
        float v2 = acc[i][2] + bias4[2];
        float v3 = acc[i][3] + bias4[3];
        if (ACT) { v0 = mish_f(v0); v1 = mish_f(v1); v2 = mish_f(v2); v3 = mish_f(v3); }
        float4 o; o.x = v0; o.y = v1; o.z = v2; o.w = v3;
        *(float4*)(C + (size_t)(row0 + ty * 8 + i) * HID + col0 + tx * 4) = o;
    }
}

// merged q + v projection, plus W fp32->fp16 conversion preamble
__global__ void __launch_bounds__(256)
gemm_qv_kernel(const float* __restrict__ node,
               const float* __restrict__ Wq, const float* __restrict__ bq,
               const float* __restrict__ Wv, const float* __restrict__ bv,
               const float* __restrict__ Wk, const float* __restrict__ We,
               float* __restrict__ Cq, float* __restrict__ Cv)
{
    // W conversion: 64 blocks x 256 threads x 4 elems = 65536
    {
        int i0 = ((blockIdx.y * gridDim.x + blockIdx.x) * 256 + threadIdx.x) * 4;
        float4 a = *(const float4*)(Wk + i0);
        float4 b = *(const float4*)(We + i0);
        union { __half2 h[2]; uint2 u; } ok, oe;
        ok.h[0] = __floats2half2_rn(a.x, a.y); ok.h[1] = __floats2half2_rn(a.z, a.w);
        oe.h[0] = __floats2half2_rn(b.x, b.y); oe.h[1] = __floats2half2_rn(b.z, b.w);
        *(uint2*)(g_wk16 + i0) = ok.u;
        *(uint2*)(g_we16 + i0) = oe.u;
    }
    int by = blockIdx.y;
    if (by < 4) gemm_core<false>(node, Wq, bq, Cq, blockIdx.x * 128, by * 64);
    else        gemm_core<false>(node, Wv, bv, Cv, blockIdx.x * 128, (by - 4) * 64);
}

__global__ void __launch_bounds__(256)
gemm_node_kernel(const float* __restrict__ A, const float* __restrict__ W,
                 const float* __restrict__ bias, float* __restrict__ C)
{
    gemm_core<true>(A, W, bias, C, blockIdx.x * 128, blockIdx.y * 64);
}

// ============================================================
// Fused softmax stats + message per (bh, 16-row tile).
// ============================================================
__global__ void __launch_bounds__(256) softmsg_kernel(
    const float* __restrict__ dist, const float* __restrict__ mask,
    const float* __restrict__ lamp)
{
    __shared__ __align__(16) float rowS[16][128];
    __shared__ float colT[128][17];
    __shared__ float mks[128];
    __shared__ float rm[16], rs[16], cm[16], cs[16];

    const int bh = blockIdx.x, b = bh >> 3;
    const int i0 = blockIdx.y * 16;
    const int t = threadIdx.x;
    const int w = t >> 5, lane = t & 31;
    const float lam = lamp[0];
    const float* Sg = g_S + (size_t)bh * 16384;

    if (t < 128) mks[t] = mask[b * 128 + t];

    #pragma unroll
    for (int r = 0; r < 2; r++) {
        int idx4 = t + 256 * r;
        int ii = idx4 >> 5, j = (idx4 & 31) * 4;
        *(float4*)&rowS[ii][j] = *(const float4*)(Sg + (i0 + ii) * 128 + j);
    }
    #pragma unroll
    for (int r = 0; r < 2; r++) {
        int idx4 = t + 256 * r;
        int j = idx4 >> 2, c = (idx4 & 3) * 4;
        float4 v = *(const float4*)(Sg + j * 128 + i0 + c);
        colT[j][c] = v.x; colT[j][c + 1] = v.y;
        colT[j][c + 2] = v.z; colT[j][c + 3] = v.w;
    }
    __syncthreads();

    #pragma unroll
    for (int u = 0; u < 2; u++) {
        int ii = 2 * w + u;
        float mx = -1e30f;
        #pragma unroll
        for (int k = 0; k < 4; k++) {
            int j = lane + 32 * k;
            if (mks[j] != 0.f) mx = fmaxf(mx, rowS[ii][j]);
        }
        #pragma unroll
        for (int s = 16; s > 0; s >>= 1) mx = fmaxf(mx, __shfl_xor_sync(0xffffffffu, mx, s));
        float sm = 0.f;
        #pragma unroll
        for (int k = 0; k < 4; k++) {
            int j = lane + 32 * k;
            if (mks[j] != 0.f) sm += __expf(rowS[ii][j] - mx);
        }
        #pragma unroll
        for (int s = 16; s > 0; s >>= 1) sm += __shfl_xor_sync(0xffffffffu, sm, s);
        if (lane == 0) { rm[ii] = mx; rs[ii] = 1.f / sm; }

        float cmx = -1e30f;
        #pragma unroll
        for (int k = 0; k < 4; k++) {
            int j = lane + 32 * k;
            if (mks[j] != 0.f) cmx = fmaxf(cmx, colT[j][ii]);
        }
        #pragma unroll
        for (int s = 16; s > 0; s >>= 1) cmx = fmaxf(cmx, __shfl_xor_sync(0xffffffffu, cmx, s));
        float csm = 0.f;
        #pragma unroll
        for (int k = 0; k < 4; k++) {
            int j = lane + 32 * k;
            if (mks[j] != 0.f) csm += __expf(colT[j][ii] - cmx);
        }
        #pragma unroll
        for (int s = 16; s > 0; s >>= 1) csm += __shfl_xor_sync(0xffffffffu, csm, s);
        if (lane == 0) { cm[ii] = cmx; cs[ii] = 1.f / csm; }
    }
    __syncthreads();

    const float* db = dist + (size_t)b * 16384 + i0 * 128;
    float* mb = g_msg + (size_t)bh * 16384 + i0 * 128;
    #pragma unroll
    for (int r = 0; r < 8; r++) {
        int idx = t + 256 * r;
        int ii = idx >> 7, j = idx & 127;
        float outv = 0.f;
        if (mks[j] != 0.f) {
            float o  = __expf(rowS[ii][j] - rm[ii]) * rs[ii];
            float in = __expf(colT[j][ii] - cm[ii]) * cs[ii];
            float val = ((i0 + ii) == j) ? in : (o + in);
            outv = val * __expf(-lam * db[idx]);
        }
        mb[idx] = outv;
    }
}

// ============================================================
// node_hidden: msg tile staged in padded smem (conflict-free)
// ============================================================
#define NODEH_SMEM ((128 * 32 + 128 * 129) * 4)
__global__ void __launch_bounds__(256) nodeh_kernel()
{
    extern __shared__ float sm_[];
    float* vs = sm_;              // 128 x 32
    float* ms = sm_ + 128 * 32;   // 128 x 129 (padded)
    const int bh = blockIdx.x;
    const int b = bh >> 3, h = bh & 7;
    const int t = threadIdx.x;
    #pragma unroll
    for (int r = 0; r < 4; r++) {
        int idx4 = t + 256 * r;
        int n = idx4 >> 3;
        int c = (idx4 & 7) * 4;
        *(float4*)&vs[n * 32 + c] =
            *(const float4*)(g_v + (size_t)(b * 128 + n) * 256 + h * 32 + c);
    }
    #pragma unroll
    for (int r = 0; r < 16; r++) {
        int idx4 = t + 256 * r;
        int i = idx4 >> 5, j = (idx4 & 31) * 4;
        float4 v = *(const float4*)(g_msg + (size_t)bh * 16384 + i * 128 + j);
        float* d = ms + i * 129 + j;
        d[0] = v.x; d[1] = v.y; d[2] = v.z; d[3] = v.w;
    }
    __syncthreads();
    const int m = t & 127;
    const int dbase = (t >> 7) * 16;
    const float* mrow = ms + m * 129;
    float acc[16];
    #pragma unroll
    for (int d = 0; d < 16; d++) acc[d] = 0.f;
    for (int n = 0; n < 128; n++) {
        float w = mrow[n];
        const float* vr = &vs[n * 32 + dbase];
        #pragma unroll
        for (int d = 0; d < 16; d++) acc[d] = fmaf(w, vr[d], acc[d]);
    }
    float* outp = g_nodeh + (size_t)(b * 128 + m) * 256 + h * 32 + dbase;
    #pragma unroll
    for (int d = 0; d < 16; d++) outp[d] = acc[d];
}

// ============================================================
extern "C" void kernel_launch(void* const* d_in, const int* in_sizes, int n_in,
                              void* d_out, int out_size)
{
    const float* node = (const float*)d_in[0];
    const float* edge = (const float*)d_in[1];
    const float* dist = (const float*)d_in[2];
    const float* mask = (const float*)d_in[3];
    const float* lam  = (const float*)d_in[4];
    const float* Wq = (const float*)d_in[5];  const float* bq = (const float*)d_in[6];
    const float* Wk = (const float*)d_in[7];  const float* bk = (const float*)d_in[8];
    const float* Wv = (const float*)d_in[9];  const float* bv = (const float*)d_in[10];
    const float* Wn = (const float*)d_in[11]; const float* bn = (const float*)d_in[12];
    const float* We = (const float*)d_in[13]; const float* be = (const float*)d_in[14];

    float* out = (float*)d_out;
    float* node_out = out;
    float* edge_out = out + (size_t)NROWS_N * HID;

    float *pq, *pv, *pnh;
    __half *pk16, *pwk16, *pwe16;
    cudaGetSymbolAddress((void**)&pq, g_q);
    cudaGetSymbolAddress((void**)&pv, g_v);
    cudaGetSymbolAddress((void**)&pnh, g_nodeh);
    cudaGetSymbolAddress((void**)&pk16, g_k16);
    cudaGetSymbolAddress((void**)&pwk16, g_wk16);
    cudaGetSymbolAddress((void**)&pwe16, g_we16);

    cudaFuncSetAttribute((const void*)tgemm_kernel<true, false, true, false, true>,
                         cudaFuncAttributeMaxDynamicSharedMemorySize, TG_SMEM);
    cudaFuncSetAttribute((const void*)tgemm_kernel<false, true, false, true, false>,
                         cudaFuncAttributeMaxDynamicSharedMemorySize, TG_SMEM);
    cudaFuncSetAttribute((const void*)nodeh_kernel,
                         cudaFuncAttributeMaxDynamicSharedMemorySize, NODEH_SMEM);

    dim3 gT(2, NROWS_E / 64);           // (2 col blocks, 2048 row blocks)

    gemm_qv_kernel<<<dim3(8, 8), 256>>>(node, Wq, bq, Wv, bv, Wk, We, pq, pv);
    tgemm_kernel<true, false, true, false, true><<<gT, 256, TG_SMEM>>>(edge, pwk16, bk, (void*)pk16);
    softmsg_kernel<<<dim3(64, 8), 256>>>(dist, mask, lam);
    tgemm_kernel<false, true, false, true, false><<<gT, 256, TG_SMEM>>>(pk16, pwe16, be, edge_out);
    nodeh_kernel<<<64, 256, NODEH_SMEM>>>();
    gemm_node_kernel<<<dim3(8, 4), 256>>>(pnh, Wn, bn, node_out);
}